// round 9
// baseline (speedup 1.0000x reference)
#include <cuda_runtime.h>
#include <cuda_bf16.h>
#include <cstdint>
#include <math.h>

#define NB    16384
#define GB    9               // batches per block
#define ROWS  126             // 9*14 used rows (padded to 128)
#define NGRP  1821            // ceil(16384/9)
#define DIM   256

// ---------------- static device scratch ----------------
__device__ __nv_bfloat16 g_Lh[4 * 256 * 64];   // pre-swizzled L hi, 4 k-chunks
__device__ __nv_bfloat16 g_Ll[4 * 256 * 64];   // pre-swizzled L lo
__device__ float g_signorm[4 * DIM];
__device__ float g_stat[NB][2][62];            // partial Gram dots per e-half
__device__ float g_rowstat[NB][14][6];         // per-row: dang, sig0..3, norm

// ---------------- helpers ----------------
__device__ __forceinline__ uint32_t smem_u32(const void* p) {
    uint32_t a;
    asm("{ .reg .u64 t; cvta.to.shared.u64 t, %1; cvt.u32.u64 %0, t; }" : "=r"(a) : "l"(p));
    return a;
}
#define SWZ128(off) ((off) ^ (((off) >> 3) & 0x70))

#define LDSM4(r, addr)                                                          \
    asm volatile("ldmatrix.sync.aligned.m8n8.x4.shared.b16 {%0,%1,%2,%3}, [%4];"\
        : "=r"((r)[0]), "=r"((r)[1]), "=r"((r)[2]), "=r"((r)[3]) : "r"(addr))

#define MMA_BF16(d, a, b)                                                       \
    asm volatile("mma.sync.aligned.m16n8k16.row.col.f32.bf16.bf16.f32 "         \
        "{%0,%1,%2,%3}, {%4,%5,%6,%7}, {%8,%9}, {%0,%1,%2,%3};"                 \
        : "+f"((d)[0]), "+f"((d)[1]), "+f"((d)[2]), "+f"((d)[3])                \
        : "r"((a)[0]), "r"((a)[1]), "r"((a)[2]), "r"((a)[3]),                   \
          "r"((b)[0]), "r"((b)[1]))

#define CP16(dst, src)                                                          \
    asm volatile("cp.async.cg.shared.global [%0], [%1], 16;"                    \
        :: "r"(dst), "l"(src) : "memory")
#define CP_COMMIT() asm volatile("cp.async.commit_group;" ::: "memory")
#define CP_WAIT0()  asm volatile("cp.async.wait_group 0;" ::: "memory")

// ---------------- prep kernels ----------------
__global__ void k_signorm(const float* __restrict__ sigs)
{
    int w = threadIdx.x >> 5, lane = threadIdx.x & 31;
    if (w < 4) {
        const float* s = sigs + w * DIM;
        float acc = 0.f;
        for (int d = lane; d < DIM; d += 32) { float v = s[d]; acc = fmaf(v, v, acc); }
        #pragma unroll
        for (int o = 16; o; o >>= 1) acc += __shfl_xor_sync(0xffffffffu, acc, o);
        float inv = 1.0f / fmaxf(sqrtf(acc), 1e-12f);
        for (int d = lane; d < DIM; d += 32) g_signorm[w * DIM + d] = s[d] * inv;
    }
}

__global__ void k_prepL(const float* __restrict__ L)
{
    int r = blockIdx.x;            // e-row 0..255
    int k = threadIdx.x;           // k 0..255
    float x = L[r * 256 + k];
    __nv_bfloat16 h = __float2bfloat16(x);
    __nv_bfloat16 l = __float2bfloat16(x - __bfloat162float(h));
    int c  = k >> 6;
    int kc = k & 63;
    uint32_t off = SWZ128((uint32_t)(r * 128 + kc * 2));
    g_Lh[c * 16384 + (off >> 1)] = h;
    g_Ll[c * 16384 + (off >> 1)] = l;
}

// ---------------- GEMM + partial-Gram kernel ----------------
// grid = (NGRP, 2 e-halves). 256 thr / 8 warps (4m x 2n), warp tile 32x64.
// smem: B e-half resident (4 chunks x hi/lo x 16KB = 128K) | A (32K) | Y-half (64K)
#define OFF_B  0
#define OFF_A  131072
#define OFF_Y  163840
#define SMEM_TOT 229376

struct RowStats { float sd, s0, s1, s2, s3, snrm; };

__device__ __forceinline__ void convert_chunk(
    const float4* pref, char* ah, char* al, int arow, int colhalf, int c,
    const float* __restrict__ dangp, RowStats& rs)
{
    #pragma unroll
    for (int j = 0; j < 8; j++) {
        float4 v = pref[j];
        int kc  = colhalf + j * 4;
        int col = c * 64 + kc;
        float4 d4 = *(const float4*)(dangp + col);
        float4 g0 = *(const float4*)(g_signorm + col);
        float4 g1 = *(const float4*)(g_signorm + 256 + col);
        float4 g2 = *(const float4*)(g_signorm + 512 + col);
        float4 g3 = *(const float4*)(g_signorm + 768 + col);
        rs.sd   = fmaf(v.x, d4.x, fmaf(v.y, d4.y, fmaf(v.z, d4.z, fmaf(v.w, d4.w, rs.sd))));
        rs.s0   = fmaf(v.x, g0.x, fmaf(v.y, g0.y, fmaf(v.z, g0.z, fmaf(v.w, g0.w, rs.s0))));
        rs.s1   = fmaf(v.x, g1.x, fmaf(v.y, g1.y, fmaf(v.z, g1.z, fmaf(v.w, g1.w, rs.s1))));
        rs.s2   = fmaf(v.x, g2.x, fmaf(v.y, g2.y, fmaf(v.z, g2.z, fmaf(v.w, g2.w, rs.s2))));
        rs.s3   = fmaf(v.x, g3.x, fmaf(v.y, g3.y, fmaf(v.z, g3.z, fmaf(v.w, g3.w, rs.s3))));
        rs.snrm = fmaf(v.x, v.x, fmaf(v.y, v.y, fmaf(v.z, v.z, fmaf(v.w, v.w, rs.snrm))));

        __nv_bfloat16 h0 = __float2bfloat16(v.x);
        __nv_bfloat16 h1 = __float2bfloat16(v.y);
        __nv_bfloat16 h2 = __float2bfloat16(v.z);
        __nv_bfloat16 h3 = __float2bfloat16(v.w);
        __nv_bfloat16 l0 = __float2bfloat16(v.x - __bfloat162float(h0));
        __nv_bfloat16 l1 = __float2bfloat16(v.y - __bfloat162float(h1));
        __nv_bfloat16 l2 = __float2bfloat16(v.z - __bfloat162float(h2));
        __nv_bfloat16 l3 = __float2bfloat16(v.w - __bfloat162float(h3));
        uint32_t off = SWZ128((uint32_t)(arow * 128 + kc * 2));
        __nv_bfloat162 hA; hA.x = h0; hA.y = h1;
        __nv_bfloat162 hB; hB.x = h2; hB.y = h3;
        __nv_bfloat162 lA; lA.x = l0; lA.y = l1;
        __nv_bfloat162 lB; lB.x = l2; lB.y = l3;
        *(__nv_bfloat162*)(ah + off)     = hA;
        *(__nv_bfloat162*)(ah + off + 4) = hB;
        *(__nv_bfloat162*)(al + off)     = lA;
        *(__nv_bfloat162*)(al + off + 4) = lB;
    }
}

__global__ void __launch_bounds__(256, 1)
k_gemm_gram(const float* __restrict__ E, const float* __restrict__ Kp,
            const float* __restrict__ danger)
{
    extern __shared__ char sm[];
    const int tid  = threadIdx.x;
    const int w    = tid >> 5, lane = tid & 31;
    const int bg   = blockIdx.x;
    const int y    = blockIdx.y;          // e-half
    const uint32_t smb = smem_u32(sm);
    float* Y = (float*)(sm + OFF_Y);

    // ---- B e-half: cp.async once (128 KB)
    {
        const char* srcH = (const char*)g_Lh + y * 16384;
        const char* srcL = (const char*)g_Ll + y * 16384;
        #pragma unroll
        for (int c = 0; c < 4; c++) {
            uint32_t dH = smb + OFF_B + c * 32768;
            uint32_t dL = dH + 16384;
            #pragma unroll
            for (int i = 0; i < 4; i++) {
                CP16(dH + (tid + i * 256) * 16, srcH + c * 32768 + (tid + i * 256) * 16);
                CP16(dL + (tid + i * 256) * 16, srcL + c * 32768 + (tid + i * 256) * 16);
            }
        }
        CP_COMMIT();
    }

    // ---- A row mapping: thread t -> row t>>1, col half (t&1)*32
    const int arow    = tid >> 1;
    const int colhalf = (tid & 1) * 32;
    const int rr      = arow < ROWS ? arow : ROWS - 1;
    const int b9      = rr / 14;
    const int wr      = rr % 14;
    int batchR = bg * GB + b9; if (batchR > NB - 1) batchR = NB - 1;
    const float* srcRow = (wr < 6) ? (E  + ((size_t)batchR * 6 + wr) * 256)
                                   : (Kp + ((size_t)batchR * 8 + (wr - 6)) * 256);
    const float* dangp = danger + (size_t)batchR * 256;

    RowStats rs = {0.f, 0.f, 0.f, 0.f, 0.f, 0.f};
    char* ahB = sm + OFF_A;
    char* alB = sm + OFF_A + 16384;

    float4 pref[8];
    {   // prologue: A chunk 0
        const float4* s4 = (const float4*)(srcRow + colhalf);
        #pragma unroll
        for (int j = 0; j < 8; j++) pref[j] = s4[j];
        convert_chunk(pref, ahB, alB, arow, colhalf, 0, dangp, rs);
    }
    CP_WAIT0();
    __syncthreads();

    // ---- warp coords + accumulators (R5-verified mapping)
    const int mbase = (w & 3) * 32;
    const int nbase = (w >> 2) * 64;
    const int arw   = mbase + (lane & 15);
    const int nrw   = nbase + (lane & 7) + ((lane >> 4) << 3);
    float acc[2][8][4];
    #pragma unroll
    for (int mt = 0; mt < 2; mt++)
        #pragma unroll
        for (int nt = 0; nt < 8; nt++)
            #pragma unroll
            for (int j = 0; j < 4; j++) acc[mt][nt][j] = 0.f;

    #pragma unroll
    for (int c = 0; c < 4; c++) {
        if (c < 3) {   // prefetch next A chunk (overlaps MMAs)
            const float4* s4 = (const float4*)(srcRow + (c + 1) * 64 + colhalf);
            #pragma unroll
            for (int j = 0; j < 8; j++) pref[j] = s4[j];
        }
        {   // MMAs on chunk c
            const uint32_t aH = smb + OFF_A, aL = aH + 16384;
            const uint32_t bH = smb + OFF_B + c * 32768, bL = bH + 16384;
            #pragma unroll
            for (int ks = 0; ks < 4; ks++) {
                uint32_t ah[2][4], al[2][4], bh[4][4], bl[4][4];
                const int akc = ks * 16 + (lane >> 4) * 8;
                const int bkc = ks * 16 + ((lane >> 3) & 1) * 8;
                #pragma unroll
                for (int mt = 0; mt < 2; mt++) {
                    uint32_t off = SWZ128((uint32_t)((arw + mt * 16) * 128 + akc * 2));
                    LDSM4(ah[mt], aH + off);
                    LDSM4(al[mt], aL + off);
                }
                #pragma unroll
                for (int g = 0; g < 4; g++) {
                    uint32_t off = SWZ128((uint32_t)((nrw + g * 16) * 128 + bkc * 2));
                    LDSM4(bh[g], bH + off);
                    LDSM4(bl[g], bL + off);
                }
                #pragma unroll
                for (int mt = 0; mt < 2; mt++)
                    #pragma unroll
                    for (int nt = 0; nt < 8; nt++) {
                        uint32_t* Bh = &bh[nt >> 1][(nt & 1) * 2];
                        uint32_t* Bl = &bl[nt >> 1][(nt & 1) * 2];
                        MMA_BF16(acc[mt][nt], ah[mt], Bh);
                        MMA_BF16(acc[mt][nt], ah[mt], Bl);
                        MMA_BF16(acc[mt][nt], al[mt], Bh);
                    }
            }
        }
        __syncthreads();
        if (c < 3) {
            convert_chunk(pref, ahB, alB, arow, colhalf, c + 1, dangp, rs);
            __syncthreads();
        }
    }

    // ---- row stats: reduce across the 2 col-half threads, store (half 0 only)
    rs.sd   += __shfl_xor_sync(~0u, rs.sd,   1, 2);
    rs.s0   += __shfl_xor_sync(~0u, rs.s0,   1, 2);
    rs.s1   += __shfl_xor_sync(~0u, rs.s1,   1, 2);
    rs.s2   += __shfl_xor_sync(~0u, rs.s2,   1, 2);
    rs.s3   += __shfl_xor_sync(~0u, rs.s3,   1, 2);
    rs.snrm += __shfl_xor_sync(~0u, rs.snrm, 1, 2);
    if (y == 0 && (tid & 1) == 0 && arow < ROWS) {
        int batch = bg * GB + arow / 14;
        if (batch < NB) {
            float* d = g_rowstat[batch][arow % 14];
            d[0] = rs.sd; d[1] = rs.s0; d[2] = rs.s1;
            d[3] = rs.s2; d[4] = rs.s3; d[5] = rs.snrm;
        }
    }

    // ---- Y-half to smem (128 rows x 128 cols)
    #pragma unroll
    for (int mt = 0; mt < 2; mt++) {
        const int row = mbase + mt * 16 + (lane >> 2);
        #pragma unroll
        for (int nt = 0; nt < 8; nt++) {
            const int col = nbase + nt * 8 + (lane & 3) * 2;
            *(float2*)(Y + row * 128 + col)       = make_float2(acc[mt][nt][0], acc[mt][nt][1]);
            *(float2*)(Y + (row + 8) * 128 + col) = make_float2(acc[mt][nt][2], acc[mt][nt][3]);
        }
    }
    __syncthreads();

    // ---- partial Gram dots over this e-half (62 per batch)
    {
        const float4* Y4 = (const float4*)Y;   // row stride 32 float4
        for (int u = w; u < GB * 62; u += 8) {
            int bl_ = u / 62, t = u - bl_ * 62;
            int rA, rB;
            if (t < 48)      { rA = bl_ * 14 + (t >> 3); rB = bl_ * 14 + 6 + (t & 7); }
            else if (t < 54) { rA = bl_ * 14 + (t - 48);     rB = rA; }
            else             { rA = bl_ * 14 + 6 + (t - 54); rB = rA; }
            float4 a = Y4[rA * 32 + lane];
            float4 b = Y4[rB * 32 + lane];
            float s = a.x * b.x + a.y * b.y + a.z * b.z + a.w * b.w;
            #pragma unroll
            for (int o = 16; o; o >>= 1) s += __shfl_xor_sync(~0u, s, o);
            if (lane == 0) {
                int batch = bg * GB + bl_;
                if (batch < NB) g_stat[batch][y][t] = s;
            }
        }
    }
}

// ---------------- final: C build + Sinkhorn + replicator (warp per batch) ----------------
__global__ void __launch_bounds__(256)
k_final(const float* __restrict__ w_prev, const float* __restrict__ fitness,
        const float* __restrict__ crisis, const float* __restrict__ proto_conf,
        float* __restrict__ out_w, float* __restrict__ out_P)
{
    const int w = threadIdx.x >> 5, lane = threadIdx.x & 31;
    const int batch = blockIdx.x * 8 + w;
    const int n = lane & 7;

    const float nK = g_stat[batch][0][54 + n] + g_stat[batch][1][54 + n];
    const float* rsk = g_rowstat[batch][6 + n];
    float kn  = fmaxf(sqrtf(rsk[5]), 1e-12f);
    float pss = fmaxf(fmaxf(rsk[1], rsk[2]), fmaxf(rsk[3], rsk[4])) / kn;
    const float pc = proto_conf[(size_t)batch * 8 + n];

    const float INV_EPS = 1.0f / (0.05f + 1e-8f);
    const float LOG_U = logf(1.0f / 6.0f + 1e-8f);
    const float LOG_V = logf(0.125f     + 1e-8f);
    float lk[6], la[6], lb = 0.0f;
    #pragma unroll
    for (int m = 0; m < 6; m++) {
        const float* rse = g_rowstat[batch][m];
        float en    = fmaxf(sqrtf(rse[5]), 1e-12f);
        float worst = fmaxf(fmaxf(rse[1], rse[2]), fmaxf(rse[3], rse[4])) / en;
        float tp    = fmaxf(worst - 0.1f, 0.0f);
        float nE    = g_stat[batch][0][48 + m] + g_stat[batch][1][48 + m];
        float cx    = g_stat[batch][0][m * 8 + n] + g_stat[batch][1][m * 8 + n];
        float msq   = nE + nK - 2.0f * cx;
        float dist  = sqrtf(fmaxf(msq, 1e-8f));
        float C     = dist - 0.5f * rse[0] + 2.0f * tp + 0.3f * pc;
        lk[m] = -C * INV_EPS;
        la[m] = 0.f;
    }

    for (int it = 0; it < 10; it++) {
        float t2[6];
        #pragma unroll
        for (int m = 0; m < 6; m++) {
            float t = lk[m] + lb;
            float r = t;
            r = fmaxf(r, __shfl_xor_sync(~0u, r, 1, 8));
            r = fmaxf(r, __shfl_xor_sync(~0u, r, 2, 8));
            r = fmaxf(r, __shfl_xor_sync(~0u, r, 4, 8));
            float s = expf(t - r);
            s += __shfl_xor_sync(~0u, s, 1, 8);
            s += __shfl_xor_sync(~0u, s, 2, 8);
            s += __shfl_xor_sync(~0u, s, 4, 8);
            la[m] = LOG_U - (r + logf(s));
            t2[m] = lk[m] + la[m];
        }
        float cm = t2[0];
        #pragma unroll
        for (int m = 1; m < 6; m++) cm = fmaxf(cm, t2[m]);
        float cs = 0.f;
        #pragma unroll
        for (int m = 0; m < 6; m++) cs += expf(t2[m] - cm);
        lb = LOG_V - (cm + logf(cs));
    }

    float pm = 0.0f;
    #pragma unroll
    for (int m = 0; m < 6; m++) {
        float p = expf(la[m] + lk[m] + lb);
        p = fminf(fmaxf(p, 0.0f), 1.0f);
        if (lane < 8) out_P[(size_t)batch * 48 + m * 8 + n] = p;
        pm += p;
    }

    float wp  = w_prev [(size_t)batch * 8 + n];
    float fit = fitness[(size_t)batch * 8 + n];
    float bl = wp * fit;
    bl += __shfl_xor_sync(~0u, bl, 1, 8);
    bl += __shfl_xor_sync(~0u, bl, 2, 8);
    bl += __shfl_xor_sync(~0u, bl, 4, 8);
    float eta = 0.05f + 0.1f * crisis[batch];
    float lt = logf(wp + 1e-8f) + eta * (fit - bl) - 0.5f * pss;
    float mx = lt;
    mx = fmaxf(mx, __shfl_xor_sync(~0u, mx, 1, 8));
    mx = fmaxf(mx, __shfl_xor_sync(~0u, mx, 2, 8));
    mx = fmaxf(mx, __shfl_xor_sync(~0u, mx, 4, 8));
    float ex = expf(lt - mx);
    float ss = ex;
    ss += __shfl_xor_sync(~0u, ss, 1, 8);
    ss += __shfl_xor_sync(~0u, ss, 2, 8);
    ss += __shfl_xor_sync(~0u, ss, 4, 8);
    float tilde = ex / ss;
    float wv = 0.7f * tilde + 0.3f * pm;
    float ws = wv;
    ws += __shfl_xor_sync(~0u, ws, 1, 8);
    ws += __shfl_xor_sync(~0u, ws, 2, 8);
    ws += __shfl_xor_sync(~0u, ws, 4, 8);
    wv = wv / (ws + 1e-8f);
    wv = fminf(fmaxf(wv, 1e-6f), 1.0f);
    if (lane < 8) out_w[(size_t)batch * 8 + n] = wv;
}

// ---------------- launch ----------------
extern "C" void kernel_launch(void* const* d_in, const int* in_sizes, int n_in,
                              void* d_out, int out_size)
{
    const float* E          = (const float*)d_in[0];
    const float* K          = (const float*)d_in[1];
    const float* danger     = (const float*)d_in[2];
    const float* w_prev     = (const float*)d_in[3];
    const float* fitness    = (const float*)d_in[4];
    const float* crisis     = (const float*)d_in[5];
    const float* proto_conf = (const float*)d_in[6];
    const float* metric_L   = (const float*)d_in[7];
    const float* self_sigs  = (const float*)d_in[8];

    float* out   = (float*)d_out;
    float* out_w = out;                       // [B, 8]
    float* out_P = out + (size_t)NB * 8;      // [B, 6, 8]

    cudaFuncSetAttribute(k_gemm_gram, cudaFuncAttributeMaxDynamicSharedMemorySize,
                         SMEM_TOT);

    k_signorm<<<1, 128>>>(self_sigs);
    k_prepL<<<256, 256>>>(metric_L);
    k_gemm_gram<<<dim3(NGRP, 2), 256, SMEM_TOT>>>(E, K, danger);
    k_final<<<NB / 8, 256>>>(w_prev, fitness, crisis, proto_conf, out_w, out_P);
}

// round 11
// speedup vs baseline: 1.1884x; 1.1884x over previous
#include <cuda_runtime.h>
#include <cuda_bf16.h>
#include <cstdint>
#include <math.h>

#define NB     16384
#define MTOK   6
#define MPROTO 8
#define DIM    256

// ---------------- static device scratch ----------------
__device__ float g_EL[(size_t)NB * MTOK * DIM];    // 96 MB
__device__ float g_KL[(size_t)NB * MPROTO * DIM];  // 128 MB
__device__ float g_signorm[4 * DIM];
__device__ __nv_bfloat16 g_Lh[4 * 256 * 64];
__device__ __nv_bfloat16 g_Ll[4 * 256 * 64];
__device__ float g_rsE[(size_t)NB * MTOK * 6];     // per-E-row: dang, sig0..3, norm
__device__ float g_rsK[(size_t)NB * MPROTO * 6];   // per-K-row

// ---------------- helpers ----------------
__device__ __forceinline__ uint32_t smem_u32(const void* p) {
    uint32_t a;
    asm("{ .reg .u64 t; cvta.to.shared.u64 t, %1; cvt.u32.u64 %0, t; }" : "=r"(a) : "l"(p));
    return a;
}
#define SWZ128(off) ((off) ^ (((off) >> 3) & 0x70))

#define LDSM4(r, addr)                                                          \
    asm volatile("ldmatrix.sync.aligned.m8n8.x4.shared.b16 {%0,%1,%2,%3}, [%4];"\
        : "=r"((r)[0]), "=r"((r)[1]), "=r"((r)[2]), "=r"((r)[3]) : "r"(addr))

#define MMA_BF16(d, a, b)                                                       \
    asm volatile("mma.sync.aligned.m16n8k16.row.col.f32.bf16.bf16.f32 "         \
        "{%0,%1,%2,%3}, {%4,%5,%6,%7}, {%8,%9}, {%0,%1,%2,%3};"                 \
        : "+f"((d)[0]), "+f"((d)[1]), "+f"((d)[2]), "+f"((d)[3])                \
        : "r"((a)[0]), "r"((a)[1]), "r"((a)[2]), "r"((a)[3]),                   \
          "r"((b)[0]), "r"((b)[1]))

#define CP16(dst, src)                                                          \
    asm volatile("cp.async.cg.shared.global [%0], [%1], 16;"                    \
        :: "r"(dst), "l"(src) : "memory")
#define CP_COMMIT() asm volatile("cp.async.commit_group;" ::: "memory")
#define CP_WAIT0()  asm volatile("cp.async.wait_group 0;" ::: "memory")

// ---------------- prep kernels ----------------
__global__ void k_signorm(const float* __restrict__ sigs)
{
    int w = threadIdx.x >> 5, lane = threadIdx.x & 31;
    if (w < 4) {
        const float* s = sigs + w * DIM;
        float acc = 0.f;
        for (int d = lane; d < DIM; d += 32) { float v = s[d]; acc = fmaf(v, v, acc); }
        #pragma unroll
        for (int o = 16; o; o >>= 1) acc += __shfl_xor_sync(0xffffffffu, acc, o);
        float inv = 1.0f / fmaxf(sqrtf(acc), 1e-12f);
        for (int d = lane; d < DIM; d += 32) g_signorm[w * DIM + d] = s[d] * inv;
    }
}

__global__ void k_prepL(const float* __restrict__ L)
{
    int r = blockIdx.x;            // e-row 0..255
    int k = threadIdx.x;           // k 0..255
    float x = L[r * 256 + k];
    __nv_bfloat16 h = __float2bfloat16(x);
    __nv_bfloat16 l = __float2bfloat16(x - __bfloat162float(h));
    int c  = k >> 6;
    int kc = k & 63;
    uint32_t off = SWZ128((uint32_t)(r * 128 + kc * 2));
    g_Lh[c * 16384 + (off >> 1)] = h;
    g_Ll[c * 16384 + (off >> 1)] = l;
}

// ---------------- GEMM kernel (R5 structure + row-stat accumulation) ----------------
// grid = (rows/128, 2). Block: 128 rows x 128 e-cols. 8 warps (4m x 2n), warp tile 32x64.
// Dyn smem: [Abuf0: Ah 16K | Al 16K][Abuf1: 32K][B: 4 chunks x (Bh 16K | Bl 16K) = 128K]
#define A_BUF   32768
#define B_BASE  65536
#define SMEM_TOT (B_BASE + 131072)

struct RowStats { float sd, s0, s1, s2, s3, snrm; };

__device__ __forceinline__ void convert_store(
    const float4* pref, char* base, int arow, int colhalf, int c,
    const float* __restrict__ dangp, RowStats& rs)
{
    #pragma unroll
    for (int j = 0; j < 8; j++) {
        float4 v = pref[j];
        int kc  = colhalf + j * 4;
        int col = c * 64 + kc;
        float4 d4 = *(const float4*)(dangp + col);
        float4 g0 = *(const float4*)(g_signorm + col);
        float4 g1 = *(const float4*)(g_signorm + 256 + col);
        float4 g2 = *(const float4*)(g_signorm + 512 + col);
        float4 g3 = *(const float4*)(g_signorm + 768 + col);
        rs.sd   = fmaf(v.x, d4.x, fmaf(v.y, d4.y, fmaf(v.z, d4.z, fmaf(v.w, d4.w, rs.sd))));
        rs.s0   = fmaf(v.x, g0.x, fmaf(v.y, g0.y, fmaf(v.z, g0.z, fmaf(v.w, g0.w, rs.s0))));
        rs.s1   = fmaf(v.x, g1.x, fmaf(v.y, g1.y, fmaf(v.z, g1.z, fmaf(v.w, g1.w, rs.s1))));
        rs.s2   = fmaf(v.x, g2.x, fmaf(v.y, g2.y, fmaf(v.z, g2.z, fmaf(v.w, g2.w, rs.s2))));
        rs.s3   = fmaf(v.x, g3.x, fmaf(v.y, g3.y, fmaf(v.z, g3.z, fmaf(v.w, g3.w, rs.s3))));
        rs.snrm = fmaf(v.x, v.x, fmaf(v.y, v.y, fmaf(v.z, v.z, fmaf(v.w, v.w, rs.snrm))));

        __nv_bfloat16 h0 = __float2bfloat16(v.x);
        __nv_bfloat16 h1 = __float2bfloat16(v.y);
        __nv_bfloat16 h2 = __float2bfloat16(v.z);
        __nv_bfloat16 h3 = __float2bfloat16(v.w);
        __nv_bfloat16 l0 = __float2bfloat16(v.x - __bfloat162float(h0));
        __nv_bfloat16 l1 = __float2bfloat16(v.y - __bfloat162float(h1));
        __nv_bfloat16 l2 = __float2bfloat16(v.z - __bfloat162float(h2));
        __nv_bfloat16 l3 = __float2bfloat16(v.w - __bfloat162float(h3));
        uint32_t off = SWZ128((uint32_t)(arow * 128 + kc * 2));
        __nv_bfloat162 hA; hA.x = h0; hA.y = h1;
        __nv_bfloat162 hB; hB.x = h2; hB.y = h3;
        __nv_bfloat162 lA; lA.x = l0; lA.y = l1;
        __nv_bfloat162 lB; lB.x = l2; lB.y = l3;
        *(__nv_bfloat162*)(base + off)             = hA;
        *(__nv_bfloat162*)(base + off + 4)         = hB;
        *(__nv_bfloat162*)(base + 16384 + off)     = lA;
        *(__nv_bfloat162*)(base + 16384 + off + 4) = lB;
    }
}

__global__ void __launch_bounds__(256, 1)
k_gemm_mma(const float* __restrict__ X, float* __restrict__ Y,
           float* __restrict__ rowstat, const float* __restrict__ danger,
           int rpb)
{
    extern __shared__ char dsm[];
    const int tid  = threadIdx.x;
    const int w    = tid >> 5, lane = tid & 31;
    const int row0 = blockIdx.x * 128;
    const int e0   = blockIdx.y * 128;
    const uint32_t smb = smem_u32(dsm);

    // ---- B: cp.async the whole 128KB (this block's e-half, all 4 k-chunks)
    {
        const char* srcH = (const char*)g_Lh + blockIdx.y * 16384;
        const char* srcL = (const char*)g_Ll + blockIdx.y * 16384;
        #pragma unroll
        for (int c = 0; c < 4; c++) {
            uint32_t dH = smb + B_BASE + c * 32768;
            uint32_t dL = dH + 16384;
            #pragma unroll
            for (int i = 0; i < 4; i++) {
                CP16(dH + (tid + i * 256) * 16, srcH + c * 32768 + (tid + i * 256) * 16);
                CP16(dL + (tid + i * 256) * 16, srcL + c * 32768 + (tid + i * 256) * 16);
            }
        }
        CP_COMMIT();
    }

    // ---- A mapping: thread t -> row t>>1, col half (t&1)*32
    const int arow    = tid >> 1;
    const int colhalf = (tid & 1) * 32;
    const int grow    = row0 + arow;
    const float* srcRow = X + (size_t)grow * DIM + colhalf;
    const float* dangBase = danger + (size_t)(grow / rpb) * 256;

    RowStats rs = {0.f, 0.f, 0.f, 0.f, 0.f, 0.f};
    float4 pref[8];

    // prologue: load + convert chunk 0 into buf 0 (overlaps B cp.async)
    {
        const float4* s4 = (const float4*)srcRow;
        #pragma unroll
        for (int j = 0; j < 8; j++) pref[j] = s4[j];
    }
    CP_WAIT0();
    convert_store(pref, dsm, arow, colhalf, 0, dangBase, rs);
    __syncthreads();

    // ---- warp coords + accumulators
    const int mbase = (w & 3) * 32;
    const int nbase = (w >> 2) * 64;
    const int arw   = mbase + (lane & 15);
    const int nrw   = nbase + (lane & 7) + ((lane >> 4) << 3);
    float acc[2][8][4];
    #pragma unroll
    for (int mt = 0; mt < 2; mt++)
        #pragma unroll
        for (int nt = 0; nt < 8; nt++)
            #pragma unroll
            for (int j = 0; j < 4; j++) acc[mt][nt][j] = 0.f;

    #pragma unroll
    for (int c = 0; c < 4; c++) {
        if (c < 3) {   // prefetch next A chunk (LDGs overlap the MMAs)
            const float4* s4 = (const float4*)(srcRow + (c + 1) * 64);
            #pragma unroll
            for (int j = 0; j < 8; j++) pref[j] = s4[j];
        }
        {   // compute on A buf (c&1), B chunk c
            const uint32_t aH = smb + (c & 1) * A_BUF;
            const uint32_t aL = aH + 16384;
            const uint32_t bH = smb + B_BASE + c * 32768;
            const uint32_t bL = bH + 16384;
            #pragma unroll
            for (int ks = 0; ks < 4; ks++) {
                uint32_t ah[2][4], al[2][4], bh[4][4], bl[4][4];
                const int akc = ks * 16 + (lane >> 4) * 8;
                const int bkc = ks * 16 + ((lane >> 3) & 1) * 8;
                #pragma unroll
                for (int mt = 0; mt < 2; mt++) {
                    uint32_t off = SWZ128((uint32_t)((arw + mt * 16) * 128 + akc * 2));
                    LDSM4(ah[mt], aH + off);
                    LDSM4(al[mt], aL + off);
                }
                #pragma unroll
                for (int g = 0; g < 4; g++) {
                    uint32_t off = SWZ128((uint32_t)((nrw + g * 16) * 128 + bkc * 2));
                    LDSM4(bh[g], bH + off);
                    LDSM4(bl[g], bL + off);
                }
                #pragma unroll
                for (int mt = 0; mt < 2; mt++)
                    #pragma unroll
                    for (int nt = 0; nt < 8; nt++) {
                        uint32_t* Bh = &bh[nt >> 1][(nt & 1) * 2];
                        uint32_t* Bl = &bl[nt >> 1][(nt & 1) * 2];
                        MMA_BF16(acc[mt][nt], ah[mt], Bh);
                        MMA_BF16(acc[mt][nt], ah[mt], Bl);
                        MMA_BF16(acc[mt][nt], al[mt], Bh);
                    }
            }
        }
        __syncthreads();
        if (c < 3) {
            convert_store(pref, dsm + ((c + 1) & 1) * A_BUF, arow, colhalf, c + 1,
                          dangBase, rs);
            __syncthreads();
        }
    }

    // ---- row stats: reduce across the 2 col-half threads, write (y==0 only)
    rs.sd   += __shfl_xor_sync(~0u, rs.sd,   1, 2);
    rs.s0   += __shfl_xor_sync(~0u, rs.s0,   1, 2);
    rs.s1   += __shfl_xor_sync(~0u, rs.s1,   1, 2);
    rs.s2   += __shfl_xor_sync(~0u, rs.s2,   1, 2);
    rs.s3   += __shfl_xor_sync(~0u, rs.s3,   1, 2);
    rs.snrm += __shfl_xor_sync(~0u, rs.snrm, 1, 2);
    if (blockIdx.y == 0 && (tid & 1) == 0) {
        float* d = rowstat + (size_t)grow * 6;
        d[0] = rs.sd; d[1] = rs.s0; d[2] = rs.s1;
        d[3] = rs.s2; d[4] = rs.s3; d[5] = rs.snrm;
    }

    // ---- store accumulators
    #pragma unroll
    for (int mt = 0; mt < 2; mt++) {
        const int row = row0 + mbase + mt * 16 + (lane >> 2);
        #pragma unroll
        for (int nt = 0; nt < 8; nt++) {
            const int col = e0 + nbase + nt * 8 + (lane & 3) * 2;
            float2 v0 = make_float2(acc[mt][nt][0], acc[mt][nt][1]);
            float2 v1 = make_float2(acc[mt][nt][2], acc[mt][nt][3]);
            *(float2*)(Y + (size_t)row * DIM + col)       = v0;
            *(float2*)(Y + (size_t)(row + 8) * DIM + col) = v1;
        }
    }
}

// ---------------- gram + final: one block per batch ----------------
__global__ void __launch_bounds__(128)
k_gramfinal(const float* __restrict__ w_prev, const float* __restrict__ fitness,
            const float* __restrict__ crisis, const float* __restrict__ proto_conf,
            float* __restrict__ out_w, float* __restrict__ out_P)
{
    __shared__ float sY[14 * 256];     // rows 0-5 = EL, 6-13 = KL
    __shared__ float sStat[62];
    const int batch = blockIdx.x;
    const int tid = threadIdx.x;
    const int w = tid >> 5, lane = tid & 31;

    // ---- stage Y rows (coalesced float4)
    {
        const float4* pe = (const float4*)(g_EL + (size_t)batch * 6 * 256);
        const float4* pk = (const float4*)(g_KL + (size_t)batch * 8 * 256);
        float4* s4 = (float4*)sY;
        #pragma unroll
        for (int i = 0; i < 3; i++) s4[tid + i * 128] = pe[tid + i * 128];
        #pragma unroll
        for (int i = 0; i < 4; i++) s4[384 + tid + i * 128] = pk[tid + i * 128];
    }
    __syncthreads();

    // ---- 62 dots (48 cross + 6 E-norm + 8 K-norm)
    {
        const float4* Y4 = (const float4*)sY;
        for (int t = w; t < 62; t += 4) {
            int rA, rB;
            if (t < 48)      { rA = t >> 3;     rB = 6 + (t & 7); }
            else if (t < 54) { rA = t - 48;     rB = rA; }
            else             { rA = 6 + t - 54; rB = rA; }
            float4 a0 = Y4[rA * 64 + lane * 2];
            float4 a1 = Y4[rA * 64 + lane * 2 + 1];
            float4 b0 = Y4[rB * 64 + lane * 2];
            float4 b1 = Y4[rB * 64 + lane * 2 + 1];
            float s = a0.x*b0.x + a0.y*b0.y + a0.z*b0.z + a0.w*b0.w
                    + a1.x*b1.x + a1.y*b1.y + a1.z*b1.z + a1.w*b1.w;
            #pragma unroll
            for (int o = 16; o; o >>= 1) s += __shfl_xor_sync(~0u, s, o);
            if (lane == 0) sStat[t] = s;
        }
    }
    __syncthreads();

    // ---- warp 0: C build + Sinkhorn + replicator
    if (w == 0) {
        const int n = lane & 7;
        const float nK = sStat[54 + n];
        const float* rsk = g_rsK + (size_t)(batch * 8 + n) * 6;
        float kn  = fmaxf(sqrtf(rsk[5]), 1e-12f);
        float pss = fmaxf(fmaxf(rsk[1], rsk[2]), fmaxf(rsk[3], rsk[4])) / kn;
        const float pc = proto_conf[(size_t)batch * 8 + n];

        const float INV_EPS = 1.0f / (0.05f + 1e-8f);
        const float LOG_U = logf(1.0f / 6.0f + 1e-8f);
        const float LOG_V = logf(0.125f     + 1e-8f);
        float lk[6], la[6], lb = 0.0f;
        #pragma unroll
        for (int m = 0; m < 6; m++) {
            const float* rse = g_rsE + (size_t)(batch * 6 + m) * 6;
            float en    = fmaxf(sqrtf(rse[5]), 1e-12f);
            float worst = fmaxf(fmaxf(rse[1], rse[2]), fmaxf(rse[3], rse[4])) / en;
            float tp    = fmaxf(worst - 0.1f, 0.0f);
            float msq   = sStat[48 + m] + nK - 2.0f * sStat[m * 8 + n];
            float dist  = sqrtf(fmaxf(msq, 1e-8f));
            float C     = dist - 0.5f * rse[0] + 2.0f * tp + 0.3f * pc;
            lk[m] = -C * INV_EPS;
            la[m] = 0.f;
        }

        for (int it = 0; it < 10; it++) {
            float t2[6];
            #pragma unroll
            for (int m = 0; m < 6; m++) {
                float t = lk[m] + lb;
                float r = t;
                r = fmaxf(r, __shfl_xor_sync(~0u, r, 1, 8));
                r = fmaxf(r, __shfl_xor_sync(~0u, r, 2, 8));
                r = fmaxf(r, __shfl_xor_sync(~0u, r, 4, 8));
                float s = expf(t - r);
                s += __shfl_xor_sync(~0u, s, 1, 8);
                s += __shfl_xor_sync(~0u, s, 2, 8);
                s += __shfl_xor_sync(~0u, s, 4, 8);
                la[m] = LOG_U - (r + logf(s));
                t2[m] = lk[m] + la[m];
            }
            float cm = t2[0];
            #pragma unroll
            for (int m = 1; m < 6; m++) cm = fmaxf(cm, t2[m]);
            float cs = 0.f;
            #pragma unroll
            for (int m = 0; m < 6; m++) cs += expf(t2[m] - cm);
            lb = LOG_V - (cm + logf(cs));
        }

        float pm = 0.0f;
        #pragma unroll
        for (int m = 0; m < 6; m++) {
            float p = expf(la[m] + lk[m] + lb);
            p = fminf(fmaxf(p, 0.0f), 1.0f);
            if (lane < 8) out_P[(size_t)batch * 48 + m * 8 + n] = p;
            pm += p;
        }

        float wp  = w_prev [(size_t)batch * 8 + n];
        float fit = fitness[(size_t)batch * 8 + n];
        float bl = wp * fit;
        bl += __shfl_xor_sync(~0u, bl, 1, 8);
        bl += __shfl_xor_sync(~0u, bl, 2, 8);
        bl += __shfl_xor_sync(~0u, bl, 4, 8);
        float eta = 0.05f + 0.1f * crisis[batch];
        float lt = logf(wp + 1e-8f) + eta * (fit - bl) - 0.5f * pss;
        float mx = lt;
        mx = fmaxf(mx, __shfl_xor_sync(~0u, mx, 1, 8));
        mx = fmaxf(mx, __shfl_xor_sync(~0u, mx, 2, 8));
        mx = fmaxf(mx, __shfl_xor_sync(~0u, mx, 4, 8));
        float ex = expf(lt - mx);
        float ss = ex;
        ss += __shfl_xor_sync(~0u, ss, 1, 8);
        ss += __shfl_xor_sync(~0u, ss, 2, 8);
        ss += __shfl_xor_sync(~0u, ss, 4, 8);
        float tilde = ex / ss;
        float wv = 0.7f * tilde + 0.3f * pm;
        float ws = wv;
        ws += __shfl_xor_sync(~0u, ws, 1, 8);
        ws += __shfl_xor_sync(~0u, ws, 2, 8);
        ws += __shfl_xor_sync(~0u, ws, 4, 8);
        wv = wv / (ws + 1e-8f);
        wv = fminf(fmaxf(wv, 1e-6f), 1.0f);
        if (lane < 8) out_w[(size_t)batch * 8 + n] = wv;
    }
}

// ---------------- launch ----------------
extern "C" void kernel_launch(void* const* d_in, const int* in_sizes, int n_in,
                              void* d_out, int out_size)
{
    const float* E          = (const float*)d_in[0];
    const float* K          = (const float*)d_in[1];
    const float* danger     = (const float*)d_in[2];
    const float* w_prev     = (const float*)d_in[3];
    const float* fitness    = (const float*)d_in[4];
    const float* crisis     = (const float*)d_in[5];
    const float* proto_conf = (const float*)d_in[6];
    const float* metric_L   = (const float*)d_in[7];
    const float* self_sigs  = (const float*)d_in[8];

    float* out   = (float*)d_out;
    float* out_w = out;                       // [B, 8]
    float* out_P = out + (size_t)NB * 8;      // [B, 6, 8]

    void *pEL = nullptr, *pKL = nullptr, *pRSE = nullptr, *pRSK = nullptr;
    cudaGetSymbolAddress(&pEL, g_EL);
    cudaGetSymbolAddress(&pKL, g_KL);
    cudaGetSymbolAddress(&pRSE, g_rsE);
    cudaGetSymbolAddress(&pRSK, g_rsK);

    cudaFuncSetAttribute(k_gemm_mma, cudaFuncAttributeMaxDynamicSharedMemorySize,
                         SMEM_TOT);

    k_signorm<<<1, 128>>>(self_sigs);
    k_prepL<<<256, 256>>>(metric_L);
    k_gemm_mma<<<dim3(NB * MTOK   / 128, 2), 256, SMEM_TOT>>>(E, (float*)pEL,
                                                              (float*)pRSE, danger, MTOK);
    k_gemm_mma<<<dim3(NB * MPROTO / 128, 2), 256, SMEM_TOT>>>(K, (float*)pKL,
                                                              (float*)pRSK, danger, MPROTO);
    k_gramfinal<<<NB, 128>>>(w_prev, fitness, crisis, proto_conf, out_w, out_P);
}

// round 13
// speedup vs baseline: 1.2242x; 1.0302x over previous
#include <cuda_runtime.h>
#include <cuda_bf16.h>
#include <cstdint>
#include <math.h>

#define NB     16384
#define MTOK   6
#define MPROTO 8
#define DIM    256

// ---------------- static device scratch ----------------
__device__ float g_EL[(size_t)NB * MTOK * DIM];    // 96 MB
__device__ float g_KL[(size_t)NB * MPROTO * DIM];  // 128 MB
__device__ float g_signorm[4 * DIM];
__device__ __nv_bfloat16 g_Lh[4 * 256 * 64];
__device__ __nv_bfloat16 g_Ll[4 * 256 * 64];

// ---------------- helpers ----------------
__device__ __forceinline__ uint32_t smem_u32(const void* p) {
    uint32_t a;
    asm("{ .reg .u64 t; cvta.to.shared.u64 t, %1; cvt.u32.u64 %0, t; }" : "=r"(a) : "l"(p));
    return a;
}
#define SWZ128(off) ((off) ^ (((off) >> 3) & 0x70))

#define LDSM4(r, addr)                                                          \
    asm volatile("ldmatrix.sync.aligned.m8n8.x4.shared.b16 {%0,%1,%2,%3}, [%4];"\
        : "=r"((r)[0]), "=r"((r)[1]), "=r"((r)[2]), "=r"((r)[3]) : "r"(addr))

#define MMA_BF16(d, a, b)                                                       \
    asm volatile("mma.sync.aligned.m16n8k16.row.col.f32.bf16.bf16.f32 "         \
        "{%0,%1,%2,%3}, {%4,%5,%6,%7}, {%8,%9}, {%0,%1,%2,%3};"                 \
        : "+f"((d)[0]), "+f"((d)[1]), "+f"((d)[2]), "+f"((d)[3])                \
        : "r"((a)[0]), "r"((a)[1]), "r"((a)[2]), "r"((a)[3]),                   \
          "r"((b)[0]), "r"((b)[1]))

#define CP16(dst, src)                                                          \
    asm volatile("cp.async.cg.shared.global [%0], [%1], 16;"                    \
        :: "r"(dst), "l"(src) : "memory")
#define CP_COMMIT() asm volatile("cp.async.commit_group;" ::: "memory")
#define CP_WAIT0()  asm volatile("cp.async.wait_group 0;" ::: "memory")

// ---------------- prep kernels ----------------
__global__ void k_signorm(const float* __restrict__ sigs)
{
    int w = threadIdx.x >> 5, lane = threadIdx.x & 31;
    if (w < 4) {
        const float* s = sigs + w * DIM;
        float acc = 0.f;
        for (int d = lane; d < DIM; d += 32) { float v = s[d]; acc = fmaf(v, v, acc); }
        #pragma unroll
        for (int o = 16; o; o >>= 1) acc += __shfl_xor_sync(0xffffffffu, acc, o);
        float inv = 1.0f / fmaxf(sqrtf(acc), 1e-12f);
        for (int d = lane; d < DIM; d += 32) g_signorm[w * DIM + d] = s[d] * inv;
    }
}

__global__ void k_prepL(const float* __restrict__ L)
{
    int r = blockIdx.x;            // e-row 0..255
    int k = threadIdx.x;           // k 0..255
    float x = L[r * 256 + k];
    __nv_bfloat16 h = __float2bfloat16(x);
    __nv_bfloat16 l = __float2bfloat16(x - __bfloat162float(h));
    int c  = k >> 6;
    int kc = k & 63;
    uint32_t off = SWZ128((uint32_t)(r * 128 + kc * 2));
    g_Lh[c * 16384 + (off >> 1)] = h;
    g_Ll[c * 16384 + (off >> 1)] = l;
}

// ---------------- GEMM kernel (exact R5 structure, 206 regs, tensor 44%) -------
// grid = (rows/128, 2). Block: 128 rows x 128 e-cols. 8 warps (4m x 2n), warp tile 32x64.
// Dyn smem: [Abuf0: Ah 16K | Al 16K][Abuf1: 32K][B: 4 chunks x (Bh 16K | Bl 16K) = 128K]
#define A_BUF   32768
#define B_BASE  65536
#define SMEM_TOT (B_BASE + 131072)

__device__ __forceinline__ void convert_store(
    const float4* pref, char* base, int arow, int colhalf)
{
    #pragma unroll
    for (int j = 0; j < 8; j++) {
        float4 v = pref[j];
        int kc = colhalf + j * 4;
        __nv_bfloat16 h0 = __float2bfloat16(v.x);
        __nv_bfloat16 h1 = __float2bfloat16(v.y);
        __nv_bfloat16 h2 = __float2bfloat16(v.z);
        __nv_bfloat16 h3 = __float2bfloat16(v.w);
        __nv_bfloat16 l0 = __float2bfloat16(v.x - __bfloat162float(h0));
        __nv_bfloat16 l1 = __float2bfloat16(v.y - __bfloat162float(h1));
        __nv_bfloat16 l2 = __float2bfloat16(v.z - __bfloat162float(h2));
        __nv_bfloat16 l3 = __float2bfloat16(v.w - __bfloat162float(h3));
        uint32_t off = SWZ128((uint32_t)(arow * 128 + kc * 2));
        __nv_bfloat162 hA; hA.x = h0; hA.y = h1;
        __nv_bfloat162 hB; hB.x = h2; hB.y = h3;
        __nv_bfloat162 lA; lA.x = l0; lA.y = l1;
        __nv_bfloat162 lB; lB.x = l2; lB.y = l3;
        *(__nv_bfloat162*)(base + off)             = hA;
        *(__nv_bfloat162*)(base + off + 4)         = hB;
        *(__nv_bfloat162*)(base + 16384 + off)     = lA;
        *(__nv_bfloat162*)(base + 16384 + off + 4) = lB;
    }
}

__global__ void __launch_bounds__(256, 1)
k_gemm_mma(const float* __restrict__ X, float* __restrict__ Y)
{
    extern __shared__ char dsm[];
    const int tid  = threadIdx.x;
    const int w    = tid >> 5, lane = tid & 31;
    const int row0 = blockIdx.x * 128;
    const int e0   = blockIdx.y * 128;
    const uint32_t smb = smem_u32(dsm);

    // ---- B: cp.async the whole 128KB (this block's e-half, all 4 k-chunks)
    {
        const char* srcH = (const char*)g_Lh + blockIdx.y * 16384;
        const char* srcL = (const char*)g_Ll + blockIdx.y * 16384;
        #pragma unroll
        for (int c = 0; c < 4; c++) {
            uint32_t dH = smb + B_BASE + c * 32768;
            uint32_t dL = dH + 16384;
            #pragma unroll
            for (int i = 0; i < 4; i++) {
                CP16(dH + (tid + i * 256) * 16, srcH + c * 32768 + (tid + i * 256) * 16);
                CP16(dL + (tid + i * 256) * 16, srcL + c * 32768 + (tid + i * 256) * 16);
            }
        }
        CP_COMMIT();
    }

    // ---- A mapping: thread t -> row t>>1, col half (t&1)*32
    const int arow    = tid >> 1;
    const int colhalf = (tid & 1) * 32;
    const float* srcRow = X + (size_t)(row0 + arow) * DIM + colhalf;

    float4 pref[8];
    {   // prologue: load chunk 0
        const float4* s4 = (const float4*)srcRow;
        #pragma unroll
        for (int j = 0; j < 8; j++) pref[j] = s4[j];
    }
    CP_WAIT0();
    convert_store(pref, dsm, arow, colhalf);
    __syncthreads();

    // ---- warp coords + accumulators
    const int mbase = (w & 3) * 32;
    const int nbase = (w >> 2) * 64;
    const int arw   = mbase + (lane & 15);
    const int nrw   = nbase + (lane & 7) + ((lane >> 4) << 3);
    float acc[2][8][4];
    #pragma unroll
    for (int mt = 0; mt < 2; mt++)
        #pragma unroll
        for (int nt = 0; nt < 8; nt++)
            #pragma unroll
            for (int j = 0; j < 4; j++) acc[mt][nt][j] = 0.f;

    #pragma unroll
    for (int c = 0; c < 4; c++) {
        if (c < 3) {   // prefetch next A chunk (LDGs overlap the MMAs)
            const float4* s4 = (const float4*)(srcRow + (c + 1) * 64);
            #pragma unroll
            for (int j = 0; j < 8; j++) pref[j] = s4[j];
        }
        {   // compute on A buf (c&1), B chunk c
            const uint32_t aH = smb + (c & 1) * A_BUF;
            const uint32_t aL = aH + 16384;
            const uint32_t bH = smb + B_BASE + c * 32768;
            const uint32_t bL = bH + 16384;
            #pragma unroll
            for (int ks = 0; ks < 4; ks++) {
                uint32_t ah[2][4], al[2][4], bh[4][4], bl[4][4];
                const int akc = ks * 16 + (lane >> 4) * 8;
                const int bkc = ks * 16 + ((lane >> 3) & 1) * 8;
                #pragma unroll
                for (int mt = 0; mt < 2; mt++) {
                    uint32_t off = SWZ128((uint32_t)((arw + mt * 16) * 128 + akc * 2));
                    LDSM4(ah[mt], aH + off);
                    LDSM4(al[mt], aL + off);
                }
                #pragma unroll
                for (int g = 0; g < 4; g++) {
                    uint32_t off = SWZ128((uint32_t)((nrw + g * 16) * 128 + bkc * 2));
                    LDSM4(bh[g], bH + off);
                    LDSM4(bl[g], bL + off);
                }
                #pragma unroll
                for (int mt = 0; mt < 2; mt++)
                    #pragma unroll
                    for (int nt = 0; nt < 8; nt++) {
                        uint32_t* Bh = &bh[nt >> 1][(nt & 1) * 2];
                        uint32_t* Bl = &bl[nt >> 1][(nt & 1) * 2];
                        MMA_BF16(acc[mt][nt], ah[mt], Bh);
                        MMA_BF16(acc[mt][nt], ah[mt], Bl);
                        MMA_BF16(acc[mt][nt], al[mt], Bh);
                    }
            }
        }
        __syncthreads();
        if (c < 3) {
            convert_store(pref, dsm + ((c + 1) & 1) * A_BUF, arow, colhalf);
            __syncthreads();
        }
    }

    // ---- store accumulators
    #pragma unroll
    for (int mt = 0; mt < 2; mt++) {
        const int row = row0 + mbase + mt * 16 + (lane >> 2);
        #pragma unroll
        for (int nt = 0; nt < 8; nt++) {
            const int col = e0 + nbase + nt * 8 + (lane & 3) * 2;
            float2 v0 = make_float2(acc[mt][nt][0], acc[mt][nt][1]);
            float2 v1 = make_float2(acc[mt][nt][2], acc[mt][nt][3]);
            *(float2*)(Y + (size_t)row * DIM + col)       = v0;
            *(float2*)(Y + (size_t)(row + 8) * DIM + col) = v1;
        }
    }
}

// ---------------- gram + stats + final: one block (256 thr) per batch ----------
__global__ void __launch_bounds__(256)
k_gramfinal(const float* __restrict__ E, const float* __restrict__ Kp,
            const float* __restrict__ danger,
            const float* __restrict__ w_prev, const float* __restrict__ fitness,
            const float* __restrict__ crisis, const float* __restrict__ proto_conf,
            float* __restrict__ out_w, float* __restrict__ out_P)
{
    __shared__ float sY[14 * 256];     // rows 0-5 = EL, 6-13 = KL
    __shared__ float sX[14 * 256];     // rows 0-5 = E,  6-13 = K (raw)
    __shared__ float sSig[4 * 256];
    __shared__ float sD[256];
    __shared__ float sStat[62];
    __shared__ float sRS[14][6];       // per-row: dang, sig0..3, norm
    const int batch = blockIdx.x;
    const int tid = threadIdx.x;
    const int w = tid >> 5, lane = tid & 31;

    // ---- stage everything (coalesced float4)
    {
        const float4* pe  = (const float4*)(g_EL + (size_t)batch * 6 * 256);
        const float4* pk  = (const float4*)(g_KL + (size_t)batch * 8 * 256);
        const float4* pre = (const float4*)(E    + (size_t)batch * 6 * 256);
        const float4* prk = (const float4*)(Kp   + (size_t)batch * 8 * 256);
        float4* y4 = (float4*)sY;
        float4* x4 = (float4*)sX;
        for (int i = tid; i < 384; i += 256) { y4[i] = pe[i];       x4[i] = pre[i]; }
        for (int i = tid; i < 512; i += 256) { y4[384 + i] = pk[i]; x4[384 + i] = prk[i]; }
        for (int i = tid; i < 256; i += 256) ((float4*)sSig)[i] = ((const float4*)g_signorm)[i];
        if (tid < 64) ((float4*)sD)[tid] = ((const float4*)(danger + (size_t)batch * 256))[tid];
    }
    __syncthreads();

    // ---- row stats: warp per row-job (14 jobs)
    for (int r = w; r < 14; r += 8) {
        const float4* row = (const float4*)(sX + r * 256);
        float4 a0 = row[lane * 2];
        float4 a1 = row[lane * 2 + 1];
        const float4* d4 = (const float4*)sD;
        const float4* s0p = (const float4*)(sSig);
        const float4* s1p = (const float4*)(sSig + 256);
        const float4* s2p = (const float4*)(sSig + 512);
        const float4* s3p = (const float4*)(sSig + 768);
        float4 b;
        float sd, s0, s1, s2, s3, sn;
        b = d4[lane * 2];       sd  = a0.x*b.x + a0.y*b.y + a0.z*b.z + a0.w*b.w;
        b = d4[lane * 2 + 1];   sd += a1.x*b.x + a1.y*b.y + a1.z*b.z + a1.w*b.w;
        b = s0p[lane * 2];      s0  = a0.x*b.x + a0.y*b.y + a0.z*b.z + a0.w*b.w;
        b = s0p[lane * 2 + 1];  s0 += a1.x*b.x + a1.y*b.y + a1.z*b.z + a1.w*b.w;
        b = s1p[lane * 2];      s1  = a0.x*b.x + a0.y*b.y + a0.z*b.z + a0.w*b.w;
        b = s1p[lane * 2 + 1];  s1 += a1.x*b.x + a1.y*b.y + a1.z*b.z + a1.w*b.w;
        b = s2p[lane * 2];      s2  = a0.x*b.x + a0.y*b.y + a0.z*b.z + a0.w*b.w;
        b = s2p[lane * 2 + 1];  s2 += a1.x*b.x + a1.y*b.y + a1.z*b.z + a1.w*b.w;
        b = s3p[lane * 2];      s3  = a0.x*b.x + a0.y*b.y + a0.z*b.z + a0.w*b.w;
        b = s3p[lane * 2 + 1];  s3 += a1.x*b.x + a1.y*b.y + a1.z*b.z + a1.w*b.w;
        sn = a0.x*a0.x + a0.y*a0.y + a0.z*a0.z + a0.w*a0.w
           + a1.x*a1.x + a1.y*a1.y + a1.z*a1.z + a1.w*a1.w;
        #pragma unroll
        for (int o = 16; o; o >>= 1) {
            sd += __shfl_xor_sync(~0u, sd, o);
            s0 += __shfl_xor_sync(~0u, s0, o);
            s1 += __shfl_xor_sync(~0u, s1, o);
            s2 += __shfl_xor_sync(~0u, s2, o);
            s3 += __shfl_xor_sync(~0u, s3, o);
            sn += __shfl_xor_sync(~0u, sn, o);
        }
        if (lane == 0) {
            sRS[r][0] = sd; sRS[r][1] = s0; sRS[r][2] = s1;
            sRS[r][3] = s2; sRS[r][4] = s3; sRS[r][5] = sn;
        }
    }

    // ---- 62 Gram dots on Y (48 cross + 6 E-norm + 8 K-norm)
    {
        const float4* Y4 = (const float4*)sY;
        for (int t = w; t < 62; t += 8) {
            int rA, rB;
            if (t < 48)      { rA = t >> 3;     rB = 6 + (t & 7); }
            else if (t < 54) { rA = t - 48;     rB = rA; }
            else             { rA = 6 + t - 54; rB = rA; }
            float4 a0 = Y4[rA * 64 + lane * 2];
            float4 a1 = Y4[rA * 64 + lane * 2 + 1];
            float4 b0 = Y4[rB * 64 + lane * 2];
            float4 b1 = Y4[rB * 64 + lane * 2 + 1];
            float s = a0.x*b0.x + a0.y*b0.y + a0.z*b0.z + a0.w*b0.w
                    + a1.x*b1.x + a1.y*b1.y + a1.z*b1.z + a1.w*b1.w;
            #pragma unroll
            for (int o = 16; o; o >>= 1) s += __shfl_xor_sync(~0u, s, o);
            if (lane == 0) sStat[t] = s;
        }
    }
    __syncthreads();

    // ---- warp 0: C build + Sinkhorn + replicator
    if (w == 0) {
        const int n = lane & 7;
        const float nK = sStat[54 + n];
        const float* rsk = sRS[6 + n];
        float kn  = fmaxf(sqrtf(rsk[5]), 1e-12f);
        float pss = fmaxf(fmaxf(rsk[1], rsk[2]), fmaxf(rsk[3], rsk[4])) / kn;
        const float pc = proto_conf[(size_t)batch * 8 + n];

        const float INV_EPS = 1.0f / (0.05f + 1e-8f);
        const float LOG_U = logf(1.0f / 6.0f + 1e-8f);
        const float LOG_V = logf(0.125f     + 1e-8f);
        float lk[6], la[6], lb = 0.0f;
        #pragma unroll
        for (int m = 0; m < 6; m++) {
            const float* rse = sRS[m];
            float en    = fmaxf(sqrtf(rse[5]), 1e-12f);
            float worst = fmaxf(fmaxf(rse[1], rse[2]), fmaxf(rse[3], rse[4])) / en;
            float tp    = fmaxf(worst - 0.1f, 0.0f);
            float msq   = sStat[48 + m] + nK - 2.0f * sStat[m * 8 + n];
            float dist  = sqrtf(fmaxf(msq, 1e-8f));
            float C     = dist - 0.5f * rse[0] + 2.0f * tp + 0.3f * pc;
            lk[m] = -C * INV_EPS;
            la[m] = 0.f;
        }

        for (int it = 0; it < 10; it++) {
            float t2[6];
            #pragma unroll
            for (int m = 0; m < 6; m++) {
                float t = lk[m] + lb;
                float r = t;
                r = fmaxf(r, __shfl_xor_sync(~0u, r, 1, 8));
                r = fmaxf(r, __shfl_xor_sync(~0u, r, 2, 8));
                r = fmaxf(r, __shfl_xor_sync(~0u, r, 4, 8));
                float s = expf(t - r);
                s += __shfl_xor_sync(~0u, s, 1, 8);
                s += __shfl_xor_sync(~0u, s, 2, 8);
                s += __shfl_xor_sync(~0u, s, 4, 8);
                la[m] = LOG_U - (r + logf(s));
                t2[m] = lk[m] + la[m];
            }
            float cm = t2[0];
            #pragma unroll
            for (int m = 1; m < 6; m++) cm = fmaxf(cm, t2[m]);
            float cs = 0.f;
            #pragma unroll
            for (int m = 0; m < 6; m++) cs += expf(t2[m] - cm);
            lb = LOG_V - (cm + logf(cs));
        }

        float pm = 0.0f;
        #pragma unroll
        for (int m = 0; m < 6; m++) {
            float p = expf(la[m] + lk[m] + lb);
            p = fminf(fmaxf(p, 0.0f), 1.0f);
            if (lane < 8) out_P[(size_t)batch * 48 + m * 8 + n] = p;
            pm += p;
        }

        float wp  = w_prev [(size_t)batch * 8 + n];
        float fit = fitness[(size_t)batch * 8 + n];
        float bl = wp * fit;
        bl += __shfl_xor_sync(~0u, bl, 1, 8);
        bl += __shfl_xor_sync(~0u, bl, 2, 8);
        bl += __shfl_xor_sync(~0u, bl, 4, 8);
        float eta = 0.05f + 0.1f * crisis[batch];
        float lt = logf(wp + 1e-8f) + eta * (fit - bl) - 0.5f * pss;
        float mx = lt;
        mx = fmaxf(mx, __shfl_xor_sync(~0u, mx, 1, 8));
        mx = fmaxf(mx, __shfl_xor_sync(~0u, mx, 2, 8));
        mx = fmaxf(mx, __shfl_xor_sync(~0u, mx, 4, 8));
        float ex = expf(lt - mx);
        float ss = ex;
        ss += __shfl_xor_sync(~0u, ss, 1, 8);
        ss += __shfl_xor_sync(~0u, ss, 2, 8);
        ss += __shfl_xor_sync(~0u, ss, 4, 8);
        float tilde = ex / ss;
        float wv = 0.7f * tilde + 0.3f * pm;
        float ws = wv;
        ws += __shfl_xor_sync(~0u, ws, 1, 8);
        ws += __shfl_xor_sync(~0u, ws, 2, 8);
        ws += __shfl_xor_sync(~0u, ws, 4, 8);
        wv = wv / (ws + 1e-8f);
        wv = fminf(fmaxf(wv, 1e-6f), 1.0f);
        if (lane < 8) out_w[(size_t)batch * 8 + n] = wv;
    }
}

// ---------------- launch ----------------
extern "C" void kernel_launch(void* const* d_in, const int* in_sizes, int n_in,
                              void* d_out, int out_size)
{
    const float* E          = (const float*)d_in[0];
    const float* K          = (const float*)d_in[1];
    const float* danger     = (const float*)d_in[2];
    const float* w_prev     = (const float*)d_in[3];
    const float* fitness    = (const float*)d_in[4];
    const float* crisis     = (const float*)d_in[5];
    const float* proto_conf = (const float*)d_in[6];
    const float* metric_L   = (const float*)d_in[7];
    const float* self_sigs  = (const float*)d_in[8];

    float* out   = (float*)d_out;
    float* out_w = out;                       // [B, 8]
    float* out_P = out + (size_t)NB * 8;      // [B, 6, 8]

    void *pEL = nullptr, *pKL = nullptr;
    cudaGetSymbolAddress(&pEL, g_EL);
    cudaGetSymbolAddress(&pKL, g_KL);

    cudaFuncSetAttribute(k_gemm_mma, cudaFuncAttributeMaxDynamicSharedMemorySize,
                         SMEM_TOT);

    k_signorm<<<1, 128>>>(self_sigs);
    k_prepL<<<256, 256>>>(metric_L);
    k_gemm_mma<<<dim3(NB * MTOK   / 128, 2), 256, SMEM_TOT>>>(E, (float*)pEL);
    k_gemm_mma<<<dim3(NB * MPROTO / 128, 2), 256, SMEM_TOT>>>(K, (float*)pKL);
    k_gramfinal<<<NB, 256>>>(E, K, danger, w_prev, fitness, crisis, proto_conf,
                             out_w, out_P);
}

// round 14
// speedup vs baseline: 1.3452x; 1.0988x over previous
#include <cuda_runtime.h>
#include <cuda_bf16.h>
#include <cstdint>
#include <math.h>

#define NB     16384
#define DIM    256

// ---------------- static device scratch ----------------
__device__ float g_signorm[4 * DIM];
__device__ __nv_bfloat16 g_Lh[4 * 256 * 64];
__device__ __nv_bfloat16 g_Ll[4 * 256 * 64];
__device__ float g_stat[NB][2][62];     // partial Gram dots per e-half (8.1 MB)

// ---------------- helpers ----------------
__device__ __forceinline__ uint32_t smem_u32(const void* p) {
    uint32_t a;
    asm("{ .reg .u64 t; cvta.to.shared.u64 t, %1; cvt.u32.u64 %0, t; }" : "=r"(a) : "l"(p));
    return a;
}
#define SWZ128(off) ((off) ^ (((off) >> 3) & 0x70))

#define LDSM4(r, addr)                                                          \
    asm volatile("ldmatrix.sync.aligned.m8n8.x4.shared.b16 {%0,%1,%2,%3}, [%4];"\
        : "=r"((r)[0]), "=r"((r)[1]), "=r"((r)[2]), "=r"((r)[3]) : "r"(addr))

#define MMA_BF16(d, a, b)                                                       \
    asm volatile("mma.sync.aligned.m16n8k16.row.col.f32.bf16.bf16.f32 "         \
        "{%0,%1,%2,%3}, {%4,%5,%6,%7}, {%8,%9}, {%0,%1,%2,%3};"                 \
        : "+f"((d)[0]), "+f"((d)[1]), "+f"((d)[2]), "+f"((d)[3])                \
        : "r"((a)[0]), "r"((a)[1]), "r"((a)[2]), "r"((a)[3]),                   \
          "r"((b)[0]), "r"((b)[1]))

#define CP16(dst, src)                                                          \
    asm volatile("cp.async.cg.shared.global [%0], [%1], 16;"                    \
        :: "r"(dst), "l"(src) : "memory")
#define CP_COMMIT() asm volatile("cp.async.commit_group;" ::: "memory")
#define CP_WAIT0()  asm volatile("cp.async.wait_group 0;" ::: "memory")

// ---------------- prep kernels ----------------
__global__ void k_signorm(const float* __restrict__ sigs)
{
    int w = threadIdx.x >> 5, lane = threadIdx.x & 31;
    if (w < 4) {
        const float* s = sigs + w * DIM;
        float acc = 0.f;
        for (int d = lane; d < DIM; d += 32) { float v = s[d]; acc = fmaf(v, v, acc); }
        #pragma unroll
        for (int o = 16; o; o >>= 1) acc += __shfl_xor_sync(0xffffffffu, acc, o);
        float inv = 1.0f / fmaxf(sqrtf(acc), 1e-12f);
        for (int d = lane; d < DIM; d += 32) g_signorm[w * DIM + d] = s[d] * inv;
    }
}

__global__ void k_prepL(const float* __restrict__ L)
{
    int r = blockIdx.x;            // e-row 0..255
    int k = threadIdx.x;           // k 0..255
    float x = L[r * 256 + k];
    __nv_bfloat16 h = __float2bfloat16(x);
    __nv_bfloat16 l = __float2bfloat16(x - __bfloat162float(h));
    int c  = k >> 6;
    int kc = k & 63;
    uint32_t off = SWZ128((uint32_t)(r * 128 + kc * 2));
    g_Lh[c * 16384 + (off >> 1)] = h;
    g_Ll[c * 16384 + (off >> 1)] = l;
}

// ---------------- unified GEMM + in-smem partial Gram ----------------
// grid = (2048, 2). Block: 112 used rows (8 batches x 14, pad to 128) x 128 e-cols.
// 8 warps (4m x 2n), warp tile 32x64. Pipeline identical to the proven R12 kernel.
// Dyn smem: [Abuf0 32K][Abuf1 32K][B: 4 x 32K = 128K]; Y (64K) overlays B after MMAs.
#define A_BUF   32768
#define B_BASE  65536
#define SMEM_TOT (B_BASE + 131072)

__device__ __forceinline__ void convert_store(
    const float4* pref, char* base, int arow, int colhalf)
{
    #pragma unroll
    for (int j = 0; j < 8; j++) {
        float4 v = pref[j];
        int kc = colhalf + j * 4;
        __nv_bfloat16 h0 = __float2bfloat16(v.x);
        __nv_bfloat16 h1 = __float2bfloat16(v.y);
        __nv_bfloat16 h2 = __float2bfloat16(v.z);
        __nv_bfloat16 h3 = __float2bfloat16(v.w);
        __nv_bfloat16 l0 = __float2bfloat16(v.x - __bfloat162float(h0));
        __nv_bfloat16 l1 = __float2bfloat16(v.y - __bfloat162float(h1));
        __nv_bfloat16 l2 = __float2bfloat16(v.z - __bfloat162float(h2));
        __nv_bfloat16 l3 = __float2bfloat16(v.w - __bfloat162float(h3));
        uint32_t off = SWZ128((uint32_t)(arow * 128 + kc * 2));
        __nv_bfloat162 hA; hA.x = h0; hA.y = h1;
        __nv_bfloat162 hB; hB.x = h2; hB.y = h3;
        __nv_bfloat162 lA; lA.x = l0; lA.y = l1;
        __nv_bfloat162 lB; lB.x = l2; lB.y = l3;
        *(__nv_bfloat162*)(base + off)             = hA;
        *(__nv_bfloat162*)(base + off + 4)         = hB;
        *(__nv_bfloat162*)(base + 16384 + off)     = lA;
        *(__nv_bfloat162*)(base + 16384 + off + 4) = lB;
    }
}

__global__ void __launch_bounds__(256, 1)
k_gemm_gram(const float* __restrict__ E, const float* __restrict__ Kp)
{
    extern __shared__ char dsm[];
    const int tid  = threadIdx.x;
    const int w    = tid >> 5, lane = tid & 31;
    const int bg   = blockIdx.x;           // batch group (8 batches)
    const int y    = blockIdx.y;           // e-half
    const uint32_t smb = smem_u32(dsm);

    // ---- B: cp.async the whole 128KB (this e-half, all 4 k-chunks)
    {
        const char* srcH = (const char*)g_Lh + y * 16384;
        const char* srcL = (const char*)g_Ll + y * 16384;
        #pragma unroll
        for (int c = 0; c < 4; c++) {
            uint32_t dH = smb + B_BASE + c * 32768;
            uint32_t dL = dH + 16384;
            #pragma unroll
            for (int i = 0; i < 4; i++) {
                CP16(dH + (tid + i * 256) * 16, srcH + c * 32768 + (tid + i * 256) * 16);
                CP16(dL + (tid + i * 256) * 16, srcL + c * 32768 + (tid + i * 256) * 16);
            }
        }
        CP_COMMIT();
    }

    // ---- A mapping: thread t -> row t>>1, col half (t&1)*32; rows pad 112..127
    const int arow    = tid >> 1;
    const int colhalf = (tid & 1) * 32;
    const int rr      = arow < 112 ? arow : 111;
    const int wr      = rr % 14;
    const int batchR  = bg * 8 + rr / 14;
    const float* srcRow = ((wr < 6) ? (E  + ((size_t)batchR * 6 + wr) * 256)
                                    : (Kp + ((size_t)batchR * 8 + (wr - 6)) * 256))
                          + colhalf;

    float4 pref[8];
    {   // prologue: load chunk 0
        const float4* s4 = (const float4*)srcRow;
        #pragma unroll
        for (int j = 0; j < 8; j++) pref[j] = s4[j];
    }
    CP_WAIT0();
    convert_store(pref, dsm, arow, colhalf);
    __syncthreads();

    // ---- warp coords + accumulators (proven mapping)
    const int mbase = (w & 3) * 32;
    const int nbase = (w >> 2) * 64;
    const int arw   = mbase + (lane & 15);
    const int nrw   = nbase + (lane & 7) + ((lane >> 4) << 3);
    float acc[2][8][4];
    #pragma unroll
    for (int mt = 0; mt < 2; mt++)
        #pragma unroll
        for (int nt = 0; nt < 8; nt++)
            #pragma unroll
            for (int j = 0; j < 4; j++) acc[mt][nt][j] = 0.f;

    #pragma unroll
    for (int c = 0; c < 4; c++) {
        if (c < 3) {   // prefetch next A chunk (LDGs overlap the MMAs)
            const float4* s4 = (const float4*)(srcRow + (c + 1) * 64);
            #pragma unroll
            for (int j = 0; j < 8; j++) pref[j] = s4[j];
        }
        {   // compute on A buf (c&1), B chunk c
            const uint32_t aH = smb + (c & 1) * A_BUF;
            const uint32_t aL = aH + 16384;
            const uint32_t bH = smb + B_BASE + c * 32768;
            const uint32_t bL = bH + 16384;
            #pragma unroll
            for (int ks = 0; ks < 4; ks++) {
                uint32_t ah[2][4], al[2][4], bh[4][4], bl[4][4];
                const int akc = ks * 16 + (lane >> 4) * 8;
                const int bkc = ks * 16 + ((lane >> 3) & 1) * 8;
                #pragma unroll
                for (int mt = 0; mt < 2; mt++) {
                    uint32_t off = SWZ128((uint32_t)((arw + mt * 16) * 128 + akc * 2));
                    LDSM4(ah[mt], aH + off);
                    LDSM4(al[mt], aL + off);
                }
                #pragma unroll
                for (int g = 0; g < 4; g++) {
                    uint32_t off = SWZ128((uint32_t)((nrw + g * 16) * 128 + bkc * 2));
                    LDSM4(bh[g], bH + off);
                    LDSM4(bl[g], bL + off);
                }
                #pragma unroll
                for (int mt = 0; mt < 2; mt++)
                    #pragma unroll
                    for (int nt = 0; nt < 8; nt++) {
                        uint32_t* Bh = &bh[nt >> 1][(nt & 1) * 2];
                        uint32_t* Bl = &bl[nt >> 1][(nt & 1) * 2];
                        MMA_BF16(acc[mt][nt], ah[mt], Bh);
                        MMA_BF16(acc[mt][nt], ah[mt], Bl);
                        MMA_BF16(acc[mt][nt], al[mt], Bh);
                    }
            }
        }
        __syncthreads();
        if (c < 3) {
            convert_store(pref, dsm + ((c + 1) & 1) * A_BUF, arow, colhalf);
            __syncthreads();
        }
    }

    // ---- store Y tile to smem over the (now dead) B region: 128 rows x 128 cols
    float* Ys = (float*)(dsm + B_BASE);
    #pragma unroll
    for (int mt = 0; mt < 2; mt++) {
        const int row = mbase + mt * 16 + (lane >> 2);
        #pragma unroll
        for (int nt = 0; nt < 8; nt++) {
            const int col = nbase + nt * 8 + (lane & 3) * 2;
            *(float2*)(Ys + row * 128 + col)       = make_float2(acc[mt][nt][0], acc[mt][nt][1]);
            *(float2*)(Ys + (row + 8) * 128 + col) = make_float2(acc[mt][nt][2], acc[mt][nt][3]);
        }
    }
    __syncthreads();

    // ---- partial Gram dots over this e-half: 8 batches x 62 jobs
    {
        const float4* Y4 = (const float4*)Ys;   // row stride 32 float4
        for (int u = w; u < 8 * 62; u += 8) {
            int bl = u / 62, t = u - bl * 62;
            int rA, rB;
            if (t < 48)      { rA = t >> 3;     rB = 6 + (t & 7); }
            else if (t < 54) { rA = t - 48;     rB = rA; }
            else             { rA = 6 + t - 54; rB = rA; }
            int base = bl * 14;
            float4 a = Y4[(base + rA) * 32 + lane];
            float4 b = Y4[(base + rB) * 32 + lane];
            float s = a.x * b.x + a.y * b.y + a.z * b.z + a.w * b.w;
            #pragma unroll
            for (int o = 16; o; o >>= 1) s += __shfl_xor_sync(~0u, s, o);
            if (lane == 0) g_stat[bg * 8 + bl][y][t] = s;
        }
    }
}

// ---------------- final: row stats + Sinkhorn + replicator (warp per batch) ----
__global__ void __launch_bounds__(256)
k_final(const float* __restrict__ E, const float* __restrict__ Kp,
        const float* __restrict__ danger,
        const float* __restrict__ w_prev, const float* __restrict__ fitness,
        const float* __restrict__ crisis, const float* __restrict__ proto_conf,
        float* __restrict__ out_w, float* __restrict__ out_P)
{
    __shared__ float sRS[8][14][6];
    const int tid = threadIdx.x;
    const int w = tid >> 5, lane = tid & 31;
    const int batch = blockIdx.x * 8 + w;

    // ---- phase A: per-row stats (warp streams its batch's 14 rows)
    {
        const float4* dg = (const float4*)(danger + (size_t)batch * 256);
        float4 d0 = dg[lane * 2], d1 = dg[lane * 2 + 1];
        const float4* gs = (const float4*)g_signorm;
        float4 g0a = gs[lane * 2],       g0b = gs[lane * 2 + 1];
        float4 g1a = gs[64 + lane * 2],  g1b = gs[64 + lane * 2 + 1];
        float4 g2a = gs[128 + lane * 2], g2b = gs[128 + lane * 2 + 1];
        float4 g3a = gs[192 + lane * 2], g3b = gs[192 + lane * 2 + 1];
        for (int r = 0; r < 14; r++) {
            const float* xr = (r < 6) ? (E  + ((size_t)batch * 6 + r) * 256)
                                      : (Kp + ((size_t)batch * 8 + (r - 6)) * 256);
            float4 a0 = ((const float4*)xr)[lane * 2];
            float4 a1 = ((const float4*)xr)[lane * 2 + 1];
            float sd = a0.x*d0.x + a0.y*d0.y + a0.z*d0.z + a0.w*d0.w
                     + a1.x*d1.x + a1.y*d1.y + a1.z*d1.z + a1.w*d1.w;
            float s0 = a0.x*g0a.x + a0.y*g0a.y + a0.z*g0a.z + a0.w*g0a.w
                     + a1.x*g0b.x + a1.y*g0b.y + a1.z*g0b.z + a1.w*g0b.w;
            float s1 = a0.x*g1a.x + a0.y*g1a.y + a0.z*g1a.z + a0.w*g1a.w
                     + a1.x*g1b.x + a1.y*g1b.y + a1.z*g1b.z + a1.w*g1b.w;
            float s2 = a0.x*g2a.x + a0.y*g2a.y + a0.z*g2a.z + a0.w*g2a.w
                     + a1.x*g2b.x + a1.y*g2b.y + a1.z*g2b.z + a1.w*g2b.w;
            float s3 = a0.x*g3a.x + a0.y*g3a.y + a0.z*g3a.z + a0.w*g3a.w
                     + a1.x*g3b.x + a1.y*g3b.y + a1.z*g3b.z + a1.w*g3b.w;
            float sn = a0.x*a0.x + a0.y*a0.y + a0.z*a0.z + a0.w*a0.w
                     + a1.x*a1.x + a1.y*a1.y + a1.z*a1.z + a1.w*a1.w;
            #pragma unroll
            for (int o = 16; o; o >>= 1) {
                sd += __shfl_xor_sync(~0u, sd, o);
                s0 += __shfl_xor_sync(~0u, s0, o);
                s1 += __shfl_xor_sync(~0u, s1, o);
                s2 += __shfl_xor_sync(~0u, s2, o);
                s3 += __shfl_xor_sync(~0u, s3, o);
                sn += __shfl_xor_sync(~0u, sn, o);
            }
            if (lane == 0) {
                sRS[w][r][0] = sd; sRS[w][r][1] = s0; sRS[w][r][2] = s1;
                sRS[w][r][3] = s2; sRS[w][r][4] = s3; sRS[w][r][5] = sn;
            }
        }
        __syncwarp();
    }

    // ---- phase B: C build + Sinkhorn + replicator (whole warp, width-8 groups)
    {
        const int n = lane & 7;
        const float nK = g_stat[batch][0][54 + n] + g_stat[batch][1][54 + n];
        const float* rsk = sRS[w][6 + n];
        float kn  = fmaxf(sqrtf(rsk[5]), 1e-12f);
        float pss = fmaxf(fmaxf(rsk[1], rsk[2]), fmaxf(rsk[3], rsk[4])) / kn;
        const float pc = proto_conf[(size_t)batch * 8 + n];

        const float INV_EPS = 1.0f / (0.05f + 1e-8f);
        const float LOG_U = logf(1.0f / 6.0f + 1e-8f);
        const float LOG_V = logf(0.125f     + 1e-8f);
        float lk[6], la[6], lb = 0.0f;
        #pragma unroll
        for (int m = 0; m < 6; m++) {
            const float* rse = sRS[w][m];
            float en    = fmaxf(sqrtf(rse[5]), 1e-12f);
            float worst = fmaxf(fmaxf(rse[1], rse[2]), fmaxf(rse[3], rse[4])) / en;
            float tp    = fmaxf(worst - 0.1f, 0.0f);
            float nE    = g_stat[batch][0][48 + m] + g_stat[batch][1][48 + m];
            float cx    = g_stat[batch][0][m * 8 + n] + g_stat[batch][1][m * 8 + n];
            float msq   = nE + nK - 2.0f * cx;
            float dist  = sqrtf(fmaxf(msq, 1e-8f));
            float C     = dist - 0.5f * rse[0] + 2.0f * tp + 0.3f * pc;
            lk[m] = -C * INV_EPS;
            la[m] = 0.f;
        }

        for (int it = 0; it < 10; it++) {
            float t2[6];
            #pragma unroll
            for (int m = 0; m < 6; m++) {
                float t = lk[m] + lb;
                float r = t;
                r = fmaxf(r, __shfl_xor_sync(~0u, r, 1, 8));
                r = fmaxf(r, __shfl_xor_sync(~0u, r, 2, 8));
                r = fmaxf(r, __shfl_xor_sync(~0u, r, 4, 8));
                float s = expf(t - r);
                s += __shfl_xor_sync(~0u, s, 1, 8);
                s += __shfl_xor_sync(~0u, s, 2, 8);
                s += __shfl_xor_sync(~0u, s, 4, 8);
                la[m] = LOG_U - (r + logf(s));
                t2[m] = lk[m] + la[m];
            }
            float cm = t2[0];
            #pragma unroll
            for (int m = 1; m < 6; m++) cm = fmaxf(cm, t2[m]);
            float cs = 0.f;
            #pragma unroll
            for (int m = 0; m < 6; m++) cs += expf(t2[m] - cm);
            lb = LOG_V - (cm + logf(cs));
        }

        float pm = 0.0f;
        #pragma unroll
        for (int m = 0; m < 6; m++) {
            float p = expf(la[m] + lk[m] + lb);
            p = fminf(fmaxf(p, 0.0f), 1.0f);
            if (lane < 8) out_P[(size_t)batch * 48 + m * 8 + n] = p;
            pm += p;
        }

        float wp  = w_prev [(size_t)batch * 8 + n];
        float fit = fitness[(size_t)batch * 8 + n];
        float bl = wp * fit;
        bl += __shfl_xor_sync(~0u, bl, 1, 8);
        bl += __shfl_xor_sync(~0u, bl, 2, 8);
        bl += __shfl_xor_sync(~0u, bl, 4, 8);
        float eta = 0.05f + 0.1f * crisis[batch];
        float lt = logf(wp + 1e-8f) + eta * (fit - bl) - 0.5f * pss;
        float mx = lt;
        mx = fmaxf(mx, __shfl_xor_sync(~0u, mx, 1, 8));
        mx = fmaxf(mx, __shfl_xor_sync(~0u, mx, 2, 8));
        mx = fmaxf(mx, __shfl_xor_sync(~0u, mx, 4, 8));
        float ex = expf(lt - mx);
        float ss = ex;
        ss += __shfl_xor_sync(~0u, ss, 1, 8);
        ss += __shfl_xor_sync(~0u, ss, 2, 8);
        ss += __shfl_xor_sync(~0u, ss, 4, 8);
        float tilde = ex / ss;
        float wv = 0.7f * tilde + 0.3f * pm;
        float ws = wv;
        ws += __shfl_xor_sync(~0u, ws, 1, 8);
        ws += __shfl_xor_sync(~0u, ws, 2, 8);
        ws += __shfl_xor_sync(~0u, ws, 4, 8);
        wv = wv / (ws + 1e-8f);
        wv = fminf(fmaxf(wv, 1e-6f), 1.0f);
        if (lane < 8) out_w[(size_t)batch * 8 + n] = wv;
    }
}

// ---------------- launch ----------------
extern "C" void kernel_launch(void* const* d_in, const int* in_sizes, int n_in,
                              void* d_out, int out_size)
{
    const float* E          = (const float*)d_in[0];
    const float* K          = (const float*)d_in[1];
    const float* danger     = (const float*)d_in[2];
    const float* w_prev     = (const float*)d_in[3];
    const float* fitness    = (const float*)d_in[4];
    const float* crisis     = (const float*)d_in[5];
    const float* proto_conf = (const float*)d_in[6];
    const float* metric_L   = (const float*)d_in[7];
    const float* self_sigs  = (const float*)d_in[8];

    float* out   = (float*)d_out;
    float* out_w = out;                       // [B, 8]
    float* out_P = out + (size_t)NB * 8;      // [B, 6, 8]

    cudaFuncSetAttribute(k_gemm_gram, cudaFuncAttributeMaxDynamicSharedMemorySize,
                         SMEM_TOT);

    k_signorm<<<1, 128>>>(self_sigs);
    k_prepL<<<256, 256>>>(metric_L);
    k_gemm_gram<<<dim3(NB / 8, 2), 256, SMEM_TOT>>>(E, K);
    k_final<<<NB / 8, 256>>>(E, K, danger, w_prev, fitness, crisis, proto_conf,
                             out_w, out_P);
}

// round 15
// speedup vs baseline: 1.4041x; 1.0438x over previous
#include <cuda_runtime.h>
#include <cuda_bf16.h>
#include <cstdint>
#include <math.h>

#define NB     16384
#define GB     9               // batches per k_gemm_gram block (126 rows of 128)
#define NGRP   1821            // ceil(16384/9)
#define DIM    256

// ---------------- static device scratch ----------------
__device__ float g_signorm[4 * DIM];
__device__ __nv_bfloat16 g_Lh[4 * 256 * 64];
__device__ __nv_bfloat16 g_Ll[4 * 256 * 64];
__device__ float g_stat[NB][2][62];     // partial Gram dots per e-half (8.1 MB)

// ---------------- helpers ----------------
__device__ __forceinline__ uint32_t smem_u32(const void* p) {
    uint32_t a;
    asm("{ .reg .u64 t; cvta.to.shared.u64 t, %1; cvt.u32.u64 %0, t; }" : "=r"(a) : "l"(p));
    return a;
}
#define SWZ128(off) ((off) ^ (((off) >> 3) & 0x70))

#define LDSM4(r, addr)                                                          \
    asm volatile("ldmatrix.sync.aligned.m8n8.x4.shared.b16 {%0,%1,%2,%3}, [%4];"\
        : "=r"((r)[0]), "=r"((r)[1]), "=r"((r)[2]), "=r"((r)[3]) : "r"(addr))

#define MMA_BF16(d, a, b)                                                       \
    asm volatile("mma.sync.aligned.m16n8k16.row.col.f32.bf16.bf16.f32 "         \
        "{%0,%1,%2,%3}, {%4,%5,%6,%7}, {%8,%9}, {%0,%1,%2,%3};"                 \
        : "+f"((d)[0]), "+f"((d)[1]), "+f"((d)[2]), "+f"((d)[3])                \
        : "r"((a)[0]), "r"((a)[1]), "r"((a)[2]), "r"((a)[3]),                   \
          "r"((b)[0]), "r"((b)[1]))

#define CP16(dst, src)                                                          \
    asm volatile("cp.async.cg.shared.global [%0], [%1], 16;"                    \
        :: "r"(dst), "l"(src) : "memory")
#define CP_COMMIT() asm volatile("cp.async.commit_group;" ::: "memory")
#define CP_WAIT0()  asm volatile("cp.async.wait_group 0;" ::: "memory")

// ---------------- prep kernels ----------------
__global__ void k_signorm(const float* __restrict__ sigs)
{
    int w = threadIdx.x >> 5, lane = threadIdx.x & 31;
    if (w < 4) {
        const float* s = sigs + w * DIM;
        float acc = 0.f;
        for (int d = lane; d < DIM; d += 32) { float v = s[d]; acc = fmaf(v, v, acc); }
        #pragma unroll
        for (int o = 16; o; o >>= 1) acc += __shfl_xor_sync(0xffffffffu, acc, o);
        float inv = 1.0f / fmaxf(sqrtf(acc), 1e-12f);
        for (int d = lane; d < DIM; d += 32) g_signorm[w * DIM + d] = s[d] * inv;
    }
}

__global__ void k_prepL(const float* __restrict__ L)
{
    int r = blockIdx.x;            // e-row 0..255
    int k = threadIdx.x;           // k 0..255
    float x = L[r * 256 + k];
    __nv_bfloat16 h = __float2bfloat16(x);
    __nv_bfloat16 l = __float2bfloat16(x - __bfloat162float(h));
    int c  = k >> 6;
    int kc = k & 63;
    uint32_t off = SWZ128((uint32_t)(r * 128 + kc * 2));
    g_Lh[c * 16384 + (off >> 1)] = h;
    g_Ll[c * 16384 + (off >> 1)] = l;
}

// ---------------- unified GEMM + in-smem partial Gram ----------------
// grid = (NGRP, 2). Block: 126 used rows (9 batches x 14, pad to 128) x 128 e-cols.
// 8 warps (4m x 2n), warp tile 32x64. Pipeline identical to the proven R12 kernel.
// Dyn smem: [Abuf0 32K][Abuf1 32K][B: 4 x 32K = 128K]; Y (64K) overlays B after MMAs.
#define A_BUF   32768
#define B_BASE  65536
#define SMEM_TOT (B_BASE + 131072)

__device__ __forceinline__ void convert_store(
    const float4* pref, char* base, int arow, int colhalf)
{
    #pragma unroll
    for (int j = 0; j < 8; j++) {
        float4 v = pref[j];
        int kc = colhalf + j * 4;
        __nv_bfloat16 h0 = __float2bfloat16(v.x);
        __nv_bfloat16 h1 = __float2bfloat16(v.y);
        __nv_bfloat16 h2 = __float2bfloat16(v.z);
        __nv_bfloat16 h3 = __float2bfloat16(v.w);
        __nv_bfloat16 l0 = __float2bfloat16(v.x - __bfloat162float(h0));
        __nv_bfloat16 l1 = __float2bfloat16(v.y - __bfloat162float(h1));
        __nv_bfloat16 l2 = __float2bfloat16(v.z - __bfloat162float(h2));
        __nv_bfloat16 l3 = __float2bfloat16(v.w - __bfloat162float(h3));
        uint32_t off = SWZ128((uint32_t)(arow * 128 + kc * 2));
        __nv_bfloat162 hA; hA.x = h0; hA.y = h1;
        __nv_bfloat162 hB; hB.x = h2; hB.y = h3;
        __nv_bfloat162 lA; lA.x = l0; lA.y = l1;
        __nv_bfloat162 lB; lB.x = l2; lB.y = l3;
        *(__nv_bfloat162*)(base + off)             = hA;
        *(__nv_bfloat162*)(base + off + 4)         = hB;
        *(__nv_bfloat162*)(base + 16384 + off)     = lA;
        *(__nv_bfloat162*)(base + 16384 + off + 4) = lB;
    }
}

__global__ void __launch_bounds__(256, 1)
k_gemm_gram(const float* __restrict__ E, const float* __restrict__ Kp)
{
    extern __shared__ char dsm[];
    const int tid  = threadIdx.x;
    const int w    = tid >> 5, lane = tid & 31;
    const int bg   = blockIdx.x;           // batch group (9 batches)
    const int y    = blockIdx.y;           // e-half
    const uint32_t smb = smem_u32(dsm);

    // ---- B: cp.async the whole 128KB (this e-half, all 4 k-chunks)
    {
        const char* srcH = (const char*)g_Lh + y * 16384;
        const char* srcL = (const char*)g_Ll + y * 16384;
        #pragma unroll
        for (int c = 0; c < 4; c++) {
            uint32_t dH = smb + B_BASE + c * 32768;
            uint32_t dL = dH + 16384;
            #pragma unroll
            for (int i = 0; i < 4; i++) {
                CP16(dH + (tid + i * 256) * 16, srcH + c * 32768 + (tid + i * 256) * 16);
                CP16(dL + (tid + i * 256) * 16, srcL + c * 32768 + (tid + i * 256) * 16);
            }
        }
        CP_COMMIT();
    }

    // ---- A mapping: thread t -> row t>>1, col half (t&1)*32; rows pad 126..127
    const int arow    = tid >> 1;
    const int colhalf = (tid & 1) * 32;
    const int rr      = arow < 126 ? arow : 125;
    const int wr      = rr % 14;
    int batchR = bg * GB + rr / 14; if (batchR > NB - 1) batchR = NB - 1;
    const float* srcRow = ((wr < 6) ? (E  + ((size_t)batchR * 6 + wr) * 256)
                                    : (Kp + ((size_t)batchR * 8 + (wr - 6)) * 256))
                          + colhalf;

    float4 pref[8];
    {   // prologue: load chunk 0
        const float4* s4 = (const float4*)srcRow;
        #pragma unroll
        for (int j = 0; j < 8; j++) pref[j] = s4[j];
    }
    CP_WAIT0();
    convert_store(pref, dsm, arow, colhalf);
    __syncthreads();

    // ---- warp coords + accumulators (proven mapping)
    const int mbase = (w & 3) * 32;
    const int nbase = (w >> 2) * 64;
    const int arw   = mbase + (lane & 15);
    const int nrw   = nbase + (lane & 7) + ((lane >> 4) << 3);
    float acc[2][8][4];
    #pragma unroll
    for (int mt = 0; mt < 2; mt++)
        #pragma unroll
        for (int nt = 0; nt < 8; nt++)
            #pragma unroll
            for (int j = 0; j < 4; j++) acc[mt][nt][j] = 0.f;

    #pragma unroll
    for (int c = 0; c < 4; c++) {
        if (c < 3) {   // prefetch next A chunk (LDGs overlap the MMAs)
            const float4* s4 = (const float4*)(srcRow + (c + 1) * 64);
            #pragma unroll
            for (int j = 0; j < 8; j++) pref[j] = s4[j];
        }
        {   // compute on A buf (c&1), B chunk c
            const uint32_t aH = smb + (c & 1) * A_BUF;
            const uint32_t aL = aH + 16384;
            const uint32_t bH = smb + B_BASE + c * 32768;
            const uint32_t bL = bH + 16384;
            #pragma unroll
            for (int ks = 0; ks < 4; ks++) {
                uint32_t ah[2][4], al[2][4], bh[4][4], bl[4][4];
                const int akc = ks * 16 + (lane >> 4) * 8;
                const int bkc = ks * 16 + ((lane >> 3) & 1) * 8;
                #pragma unroll
                for (int mt = 0; mt < 2; mt++) {
                    uint32_t off = SWZ128((uint32_t)((arw + mt * 16) * 128 + akc * 2));
                    LDSM4(ah[mt], aH + off);
                    LDSM4(al[mt], aL + off);
                }
                #pragma unroll
                for (int g = 0; g < 4; g++) {
                    uint32_t off = SWZ128((uint32_t)((nrw + g * 16) * 128 + bkc * 2));
                    LDSM4(bh[g], bH + off);
                    LDSM4(bl[g], bL + off);
                }
                #pragma unroll
                for (int mt = 0; mt < 2; mt++)
                    #pragma unroll
                    for (int nt = 0; nt < 8; nt++) {
                        uint32_t* Bh = &bh[nt >> 1][(nt & 1) * 2];
                        uint32_t* Bl = &bl[nt >> 1][(nt & 1) * 2];
                        MMA_BF16(acc[mt][nt], ah[mt], Bh);
                        MMA_BF16(acc[mt][nt], ah[mt], Bl);
                        MMA_BF16(acc[mt][nt], al[mt], Bh);
                    }
            }
        }
        __syncthreads();
        if (c < 3) {
            convert_store(pref, dsm + ((c + 1) & 1) * A_BUF, arow, colhalf);
            __syncthreads();
        }
    }

    // ---- store Y tile to smem over the (now dead) B region: 128 rows x 128 cols
    float* Ys = (float*)(dsm + B_BASE);
    #pragma unroll
    for (int mt = 0; mt < 2; mt++) {
        const int row = mbase + mt * 16 + (lane >> 2);
        #pragma unroll
        for (int nt = 0; nt < 8; nt++) {
            const int col = nbase + nt * 8 + (lane & 3) * 2;
            *(float2*)(Ys + row * 128 + col)       = make_float2(acc[mt][nt][0], acc[mt][nt][1]);
            *(float2*)(Ys + (row + 8) * 128 + col) = make_float2(acc[mt][nt][2], acc[mt][nt][3]);
        }
    }
    __syncthreads();

    // ---- partial Gram dots over this e-half: 9 batches x 62 jobs
    {
        const float4* Y4 = (const float4*)Ys;   // row stride 32 float4
        for (int u = w; u < GB * 62; u += 8) {
            int bl = u / 62, t = u - bl * 62;
            int rA, rB;
            if (t < 48)      { rA = t >> 3;     rB = 6 + (t & 7); }
            else if (t < 54) { rA = t - 48;     rB = rA; }
            else             { rA = 6 + t - 54; rB = rA; }
            int base = bl * 14;
            float4 a = Y4[(base + rA) * 32 + lane];
            float4 b = Y4[(base + rB) * 32 + lane];
            float s = a.x * b.x + a.y * b.y + a.z * b.z + a.w * b.w;
            #pragma unroll
            for (int o = 16; o; o >>= 1) s += __shfl_xor_sync(~0u, s, o);
            if (lane == 0) {
                int batch = bg * GB + bl;
                if (batch < NB) g_stat[batch][y][t] = s;
            }
        }
    }
}

// ---------------- final: row stats + Sinkhorn + replicator (warp per batch) ----
__global__ void __launch_bounds__(256)
k_final(const float* __restrict__ E, const float* __restrict__ Kp,
        const float* __restrict__ danger,
        const float* __restrict__ w_prev, const float* __restrict__ fitness,
        const float* __restrict__ crisis, const float* __restrict__ proto_conf,
        float* __restrict__ out_w, float* __restrict__ out_P)
{
    __shared__ float sRS[8][14][6];
    const int tid = threadIdx.x;
    const int w = tid >> 5, lane = tid & 31;
    const int batch = blockIdx.x * 8 + w;

    // ---- phase A: per-row stats (warp streams its batch's 14 rows)
    {
        const float4* dg = (const float4*)(danger + (size_t)batch * 256);
        float4 d0 = dg[lane * 2], d1 = dg[lane * 2 + 1];
        const float4* gs = (const float4*)g_signorm;
        float4 g0a = gs[lane * 2],       g0b = gs[lane * 2 + 1];
        float4 g1a = gs[64 + lane * 2],  g1b = gs[64 + lane * 2 + 1];
        float4 g2a = gs[128 + lane * 2], g2b = gs[128 + lane * 2 + 1];
        float4 g3a = gs[192 + lane * 2], g3b = gs[192 + lane * 2 + 1];
        for (int r = 0; r < 14; r++) {
            const float* xr = (r < 6) ? (E  + ((size_t)batch * 6 + r) * 256)
                                      : (Kp + ((size_t)batch * 8 + (r - 6)) * 256);
            float4 a0 = ((const float4*)xr)[lane * 2];
            float4 a1 = ((const float4*)xr)[lane * 2 + 1];
            float sd = a0.x*d0.x + a0.y*d0.y + a0.z*d0.z + a0.w*d0.w
                     + a1.x*d1.x + a1.y*d1.y + a1.z*d1.z + a1.w*d1.w;
            float s0 = a0.x*g0a.x + a0.y*g0a.y + a0.z*g0a.z + a0.w*g0a.w
                     + a1.x*g0b.x + a1.y*g0b.y + a1.z*g0b.z + a1.w*g0b.w;
            float s1 = a0.x*g1a.x + a0.y*g1a.y + a0.z*g1a.z + a0.w*g1a.w
                     + a1.x*g1b.x + a1.y*g1b.y + a1.z*g1b.z + a1.w*g1b.w;
            float s2 = a0.x*g2a.x + a0.y*g2a.y + a0.z*g2a.z + a0.w*g2a.w
                     + a1.x*g2b.x + a1.y*g2b.y + a1.z*g2b.z + a1.w*g2b.w;
            float s3 = a0.x*g3a.x + a0.y*g3a.y + a0.z*g3a.z + a0.w*g3a.w
                     + a1.x*g3b.x + a1.y*g3b.y + a1.z*g3b.z + a1.w*g3b.w;
            float sn = a0.x*a0.x + a0.y*a0.y + a0.z*a0.z + a0.w*a0.w
                     + a1.x*a1.x + a1.y*a1.y + a1.z*a1.z + a1.w*a1.w;
            #pragma unroll
            for (int o = 16; o; o >>= 1) {
                sd += __shfl_xor_sync(~0u, sd, o);
                s0 += __shfl_xor_sync(~0u, s0, o);
                s1 += __shfl_xor_sync(~0u, s1, o);
                s2 += __shfl_xor_sync(~0u, s2, o);
                s3 += __shfl_xor_sync(~0u, s3, o);
                sn += __shfl_xor_sync(~0u, sn, o);
            }
            if (lane == 0) {
                sRS[w][r][0] = sd; sRS[w][r][1] = s0; sRS[w][r][2] = s1;
                sRS[w][r][3] = s2; sRS[w][r][4] = s3; sRS[w][r][5] = sn;
            }
        }
        __syncwarp();
    }

    // ---- phase B: C build + Sinkhorn + replicator (whole warp, width-8 groups)
    {
        const int n = lane & 7;
        const float nK = g_stat[batch][0][54 + n] + g_stat[batch][1][54 + n];
        const float* rsk = sRS[w][6 + n];
        float kn  = fmaxf(sqrtf(rsk[5]), 1e-12f);
        float pss = fmaxf(fmaxf(rsk[1], rsk[2]), fmaxf(rsk[3], rsk[4])) / kn;
        const float pc = proto_conf[(size_t)batch * 8 + n];

        const float INV_EPS = 1.0f / (0.05f + 1e-8f);
        const float LOG_U = logf(1.0f / 6.0f + 1e-8f);
        const float LOG_V = logf(0.125f     + 1e-8f);
        float lk[6], la[6], lb = 0.0f;
        #pragma unroll
        for (int m = 0; m < 6; m++) {
            const float* rse = sRS[w][m];
            float en    = fmaxf(sqrtf(rse[5]), 1e-12f);
            float worst = fmaxf(fmaxf(rse[1], rse[2]), fmaxf(rse[3], rse[4])) / en;
            float tp    = fmaxf(worst - 0.1f, 0.0f);
            float nE    = g_stat[batch][0][48 + m] + g_stat[batch][1][48 + m];
            float cx    = g_stat[batch][0][m * 8 + n] + g_stat[batch][1][m * 8 + n];
            float msq   = nE + nK - 2.0f * cx;
            float dist  = sqrtf(fmaxf(msq, 1e-8f));
            float C     = dist - 0.5f * rse[0] + 2.0f * tp + 0.3f * pc;
            lk[m] = -C * INV_EPS;
            la[m] = 0.f;
        }

        for (int it = 0; it < 10; it++) {
            float t2[6];
            #pragma unroll
            for (int m = 0; m < 6; m++) {
                float t = lk[m] + lb;
                float r = t;
                r = fmaxf(r, __shfl_xor_sync(~0u, r, 1, 8));
                r = fmaxf(r, __shfl_xor_sync(~0u, r, 2, 8));
                r = fmaxf(r, __shfl_xor_sync(~0u, r, 4, 8));
                float s = expf(t - r);
                s += __shfl_xor_sync(~0u, s, 1, 8);
                s += __shfl_xor_sync(~0u, s, 2, 8);
                s += __shfl_xor_sync(~0u, s, 4, 8);
                la[m] = LOG_U - (r + logf(s));
                t2[m] = lk[m] + la[m];
            }
            float cm = t2[0];
            #pragma unroll
            for (int m = 1; m < 6; m++) cm = fmaxf(cm, t2[m]);
            float cs = 0.f;
            #pragma unroll
            for (int m = 0; m < 6; m++) cs += expf(t2[m] - cm);
            lb = LOG_V - (cm + logf(cs));
        }

        float pm = 0.0f;
        #pragma unroll
        for (int m = 0; m < 6; m++) {
            float p = expf(la[m] + lk[m] + lb);
            p = fminf(fmaxf(p, 0.0f), 1.0f);
            if (lane < 8) out_P[(size_t)batch * 48 + m * 8 + n] = p;
            pm += p;
        }

        float wp  = w_prev [(size_t)batch * 8 + n];
        float fit = fitness[(size_t)batch * 8 + n];
        float bl = wp * fit;
        bl += __shfl_xor_sync(~0u, bl, 1, 8);
        bl += __shfl_xor_sync(~0u, bl, 2, 8);
        bl += __shfl_xor_sync(~0u, bl, 4, 8);
        float eta = 0.05f + 0.1f * crisis[batch];
        float lt = logf(wp + 1e-8f) + eta * (fit - bl) - 0.5f * pss;
        float mx = lt;
        mx = fmaxf(mx, __shfl_xor_sync(~0u, mx, 1, 8));
        mx = fmaxf(mx, __shfl_xor_sync(~0u, mx, 2, 8));
        mx = fmaxf(mx, __shfl_xor_sync(~0u, mx, 4, 8));
        float ex = expf(lt - mx);
        float ss = ex;
        ss += __shfl_xor_sync(~0u, ss, 1, 8);
        ss += __shfl_xor_sync(~0u, ss, 2, 8);
        ss += __shfl_xor_sync(~0u, ss, 4, 8);
        float tilde = ex / ss;
        float wv = 0.7f * tilde + 0.3f * pm;
        float ws = wv;
        ws += __shfl_xor_sync(~0u, ws, 1, 8);
        ws += __shfl_xor_sync(~0u, ws, 2, 8);
        ws += __shfl_xor_sync(~0u, ws, 4, 8);
        wv = wv / (ws + 1e-8f);
        wv = fminf(fmaxf(wv, 1e-6f), 1.0f);
        if (lane < 8) out_w[(size_t)batch * 8 + n] = wv;
    }
}

// ---------------- launch ----------------
extern "C" void kernel_launch(void* const* d_in, const int* in_sizes, int n_in,
                              void* d_out, int out_size)
{
    const float* E          = (const float*)d_in[0];
    const float* K          = (const float*)d_in[1];
    const float* danger     = (const float*)d_in[2];
    const float* w_prev     = (const float*)d_in[3];
    const float* fitness    = (const float*)d_in[4];
    const float* crisis     = (const float*)d_in[5];
    const float* proto_conf = (const float*)d_in[6];
    const float* metric_L   = (const float*)d_in[7];
    const float* self_sigs  = (const float*)d_in[8];

    float* out   = (float*)d_out;
    float* out_w = out;                       // [B, 8]
    float* out_P = out + (size_t)NB * 8;      // [B, 6, 8]

    cudaFuncSetAttribute(k_gemm_gram, cudaFuncAttributeMaxDynamicSharedMemorySize,
                         SMEM_TOT);

    k_signorm<<<1, 128>>>(self_sigs);
    k_prepL<<<256, 256>>>(metric_L);
    k_gemm_gram<<<dim3(NGRP, 2), 256, SMEM_TOT>>>(E, K);
    k_final<<<NB / 8, 256>>>(E, K, danger, w_prev, fitness, crisis, proto_conf,
                             out_w, out_P);
}